// round 2
// baseline (speedup 1.0000x reference)
#include <cuda_runtime.h>
#include <cuda_bf16.h>

#define NN 50000
#define EE 800000
#define FF 128
#define HH 256
#define CC 40
#define NB ((NN + 1023) / 1024)   // 49 scan blocks

// ---------------- scratch (device globals; no runtime allocation) ----------
__device__ float g_bufA[(size_t)NN * HH];   // agg(x) / h2
__device__ float g_bufB[(size_t)NN * HH];   // relu(h1) / agg2
__device__ int   g_deg[NN];
__device__ float g_dinv[NN];
__device__ int   g_rowptr[NN];
__device__ int   g_cursor[NN];
__device__ int   g_partials[64];
__device__ int   g_csrc[EE];

// ---------------- CSR build ------------------------------------------------
__global__ void zero_deg_kernel() {
    int i = blockIdx.x * blockDim.x + threadIdx.x;
    if (i < NN) g_deg[i] = 0;
}

__global__ void count_deg_kernel(const int* __restrict__ dst) {
    int e = blockIdx.x * blockDim.x + threadIdx.x;
    if (e < EE) atomicAdd(&g_deg[dst[e]], 1);
}

__global__ void dinv_kernel() {
    int i = blockIdx.x * blockDim.x + threadIdx.x;
    if (i < NN) g_dinv[i] = rsqrtf((float)g_deg[i] + 1.0f);
}

__global__ void scan_blocks_kernel() {
    __shared__ int sh[1024];
    int t = threadIdx.x;
    int i = blockIdx.x * 1024 + t;
    int v = (i < NN) ? g_deg[i] : 0;
    sh[t] = v;
    __syncthreads();
    #pragma unroll
    for (int off = 1; off < 1024; off <<= 1) {
        int add = (t >= off) ? sh[t - off] : 0;
        __syncthreads();
        sh[t] += add;
        __syncthreads();
    }
    if (i < NN) g_rowptr[i] = sh[t] - v;   // exclusive prefix
    if (t == 1023) g_partials[blockIdx.x] = sh[1023];
}

__global__ void scan_partials_kernel() {
    if (threadIdx.x == 0 && blockIdx.x == 0) {
        int acc = 0;
        for (int b = 0; b < NB; b++) {
            int t = g_partials[b];
            g_partials[b] = acc;
            acc += t;
        }
    }
}

__global__ void add_offsets_kernel() {
    int i = blockIdx.x * blockDim.x + threadIdx.x;
    if (i < NN) {
        int v = g_rowptr[i] + g_partials[i >> 10];
        g_rowptr[i] = v;
        g_cursor[i] = v;
    }
}

__global__ void fill_csr_kernel(const int* __restrict__ src, const int* __restrict__ dst) {
    int e = blockIdx.x * blockDim.x + threadIdx.x;
    if (e < EE) {
        int pos = atomicAdd(&g_cursor[dst[e]], 1);
        g_csrc[pos] = src[e];
    }
}

// ---------------- packed f32x2 helpers -------------------------------------
__device__ __forceinline__ void ffma2(unsigned long long& d,
                                      unsigned long long a,
                                      unsigned long long b) {
    asm("fma.rn.f32x2 %0, %1, %2, %0;" : "+l"(d) : "l"(a), "l"(b));
}

__device__ __forceinline__ float2 unpack2(unsigned long long v) {
    float2 p;
    asm("mov.b64 {%0, %1}, %2;" : "=f"(p.x), "=f"(p.y) : "l"(v));
    return p;
}

// ---------------- GEMM: C[M,N] = A[M,K] * B[N,K]^T (+bias, relu) ----------
// Packed fp32x2 FMA: thread fragment = 4 row-pairs x 8 columns.
// Row m = bm + ty*8 + {0..7}; column n = bn + tx + 16*jj.
#define BM 128
#define BN 128
#define BK 16

__global__ __launch_bounds__(256, 2)
void gemm_nt_f2_kernel(const float* __restrict__ A, const float* __restrict__ B,
                       const float* __restrict__ bias, float* __restrict__ C,
                       int M, int N, int K, int relu) {
    __shared__ float As[BK][BM + 4];
    __shared__ float Bd[BK][2 * BN];   // duplicated pairs: Bd[k][2n]=Bd[k][2n+1]=B[n][k]

    int bm = blockIdx.y * BM;
    int bn = blockIdx.x * BN;
    int tid = threadIdx.x;          // 0..255
    int tx = tid & 15;              // 0..15
    int ty = tid >> 4;              // 0..15

    unsigned long long acc[4][8];
    #pragma unroll
    for (int i = 0; i < 4; i++)
        #pragma unroll
        for (int j = 0; j < 8; j++) acc[i][j] = 0ull;   // = (0.0f, 0.0f)

    for (int k0 = 0; k0 < K; k0 += BK) {
        // A tile: 128 rows x 16 k -> 512 float4 over 256 threads
        #pragma unroll
        for (int idx = tid; idx < BM * BK / 4; idx += 256) {
            int r = idx >> 2;
            int kq = idx & 3;
            int m = bm + r;
            float4 v = make_float4(0.f, 0.f, 0.f, 0.f);
            if (m < M) v = *(const float4*)&A[(size_t)m * K + k0 + kq * 4];
            As[kq * 4 + 0][r] = v.x;
            As[kq * 4 + 1][r] = v.y;
            As[kq * 4 + 2][r] = v.z;
            As[kq * 4 + 3][r] = v.w;
        }
        // B tile with duplication
        #pragma unroll
        for (int idx = tid; idx < BN * BK / 4; idx += 256) {
            int r = idx >> 2;
            int kq = idx & 3;
            int n = bn + r;
            float4 v = make_float4(0.f, 0.f, 0.f, 0.f);
            if (n < N) v = *(const float4*)&B[(size_t)n * K + k0 + kq * 4];
            *(float2*)&Bd[kq * 4 + 0][2 * r] = make_float2(v.x, v.x);
            *(float2*)&Bd[kq * 4 + 1][2 * r] = make_float2(v.y, v.y);
            *(float2*)&Bd[kq * 4 + 2][2 * r] = make_float2(v.z, v.z);
            *(float2*)&Bd[kq * 4 + 3][2 * r] = make_float2(v.w, v.w);
        }
        __syncthreads();

        #pragma unroll
        for (int kk = 0; kk < BK; kk++) {
            ulonglong2 a01 = *(const ulonglong2*)&As[kk][ty * 8];
            ulonglong2 a23 = *(const ulonglong2*)&As[kk][ty * 8 + 4];
            unsigned long long a[4] = {a01.x, a01.y, a23.x, a23.y};
            #pragma unroll
            for (int jj = 0; jj < 8; jj++) {
                unsigned long long bd =
                    *(const unsigned long long*)&Bd[kk][2 * (tx + 16 * jj)];
                ffma2(acc[0][jj], a[0], bd);
                ffma2(acc[1][jj], a[1], bd);
                ffma2(acc[2][jj], a[2], bd);
                ffma2(acc[3][jj], a[3], bd);
            }
        }
        __syncthreads();
    }

    // epilogue
    #pragma unroll
    for (int jj = 0; jj < 8; jj++) {
        int col = bn + tx + 16 * jj;
        if (col >= N) continue;
        float bv = bias ? bias[col] : 0.0f;
        #pragma unroll
        for (int ip = 0; ip < 4; ip++) {
            float2 p = unpack2(acc[ip][jj]);
            int m0 = bm + ty * 8 + 2 * ip;
            float v0 = p.x + bv;
            float v1 = p.y + bv;
            if (relu) { v0 = fmaxf(v0, 0.0f); v1 = fmaxf(v1, 0.0f); }
            if (m0 < M)     C[(size_t)m0 * N + col] = v0;
            if (m0 + 1 < M) C[(size_t)(m0 + 1) * N + col] = v1;
        }
    }
}

// ---------------- aggregation: block per node, CH channels -----------------
template<int CH>
__global__ __launch_bounds__(CH)
void aggregate_kernel(const float* __restrict__ h, const float* __restrict__ bias,
                      float* __restrict__ out) {
    int i = blockIdx.x;
    int c = threadIdx.x;
    __shared__ int   s_src[CH];
    __shared__ float s_w[CH];

    int start = g_rowptr[i];
    int d = g_deg[i];
    float di = g_dinv[i];
    float acc = 0.0f;

    for (int base = 0; base < d; base += CH) {
        int n = d - base;
        if (n > CH) n = CH;
        __syncthreads();
        if (c < n) {
            int s = g_csrc[start + base + c];
            s_src[c] = s;
            s_w[c] = g_dinv[s];
        }
        __syncthreads();
        #pragma unroll 4
        for (int j = 0; j < n; j++)
            acc += s_w[j] * h[(size_t)s_src[j] * CH + c];
    }

    float v = di * acc + di * di * h[(size_t)i * CH + c];
    if (bias) v += bias[c];
    out[(size_t)i * CH + c] = v;
}

// ---------------- launch ---------------------------------------------------
extern "C" void kernel_launch(void* const* d_in, const int* in_sizes, int n_in,
                              void* d_out, int out_size) {
    const float* x    = (const float*)d_in[0];
    const int*   ei   = (const int*)d_in[1];
    const float* W1   = (const float*)d_in[2];
    const float* b1   = (const float*)d_in[3];
    const float* W2   = (const float*)d_in[4];
    const float* b2   = (const float*)d_in[5];
    const float* Wout = (const float*)d_in[6];
    const float* bout = (const float*)d_in[7];
    float* out = (float*)d_out;

    const int* src = ei;         // edge_index[0]
    const int* dst = ei + EE;    // edge_index[1]

    float* bufA;  cudaGetSymbolAddress((void**)&bufA, g_bufA);
    float* bufB;  cudaGetSymbolAddress((void**)&bufB, g_bufB);

    // ---- CSR build ----
    zero_deg_kernel<<<(NN + 255) / 256, 256>>>();
    count_deg_kernel<<<(EE + 255) / 256, 256>>>(dst);
    dinv_kernel<<<(NN + 255) / 256, 256>>>();
    scan_blocks_kernel<<<NB, 1024>>>();
    scan_partials_kernel<<<1, 32>>>();
    add_offsets_kernel<<<(NN + 255) / 256, 256>>>();
    fill_csr_kernel<<<(EE + 255) / 256, 256>>>(src, dst);

    // ---- layer 1: agg(x) first (F=128 halves gather traffic), then GEMM
    //      with fused bias + relu: bufB = relu(agg(x) @ W1^T + b1) ----
    aggregate_kernel<FF><<<NN, FF>>>(x, nullptr, bufA);
    {
        dim3 grid((HH + BN - 1) / BN, (NN + BM - 1) / BM);
        gemm_nt_f2_kernel<<<grid, 256>>>(bufA, W1, b1, bufB, NN, HH, FF, 1);
    }

    // ---- layer 2: h2 = bufB @ W2^T -> bufA ; agg2 + b2 -> bufB ----
    {
        dim3 grid((HH + BN - 1) / BN, (NN + BM - 1) / BM);
        gemm_nt_f2_kernel<<<grid, 256>>>(bufB, W2, nullptr, bufA, NN, HH, HH, 0);
    }
    aggregate_kernel<HH><<<NN, HH>>>(bufA, b2, bufB);

    // ---- output: out = bufB @ Wout^T + bout ----
    {
        dim3 grid((CC + BN - 1) / BN, (NN + BM - 1) / BM);
        gemm_nt_f2_kernel<<<grid, 256>>>(bufB, Wout, bout, out, NN, CC, HH, 0);
    }
}

// round 3
// speedup vs baseline: 1.7403x; 1.7403x over previous
#include <cuda_runtime.h>
#include <cuda_bf16.h>
#include <cstdint>

#define NN 50000
#define EE 800000
#define FF 128
#define HH 256
#define CC 40
#define NB ((NN + 1023) / 1024)   // 49 scan blocks

// ---------------- scratch (device globals; no runtime allocation) ----------
__device__ float g_bufA[(size_t)NN * HH];   // agg(x) / h2
__device__ float g_bufB[(size_t)NN * HH];   // relu(h1) / agg2
__device__ __nv_bfloat16 g_a16[(size_t)NN * 3 * HH];   // split activations (max K'=768)
__device__ __nv_bfloat16 g_w16[(size_t)HH * 3 * HH];   // split weights (max 256x768)
__device__ int   g_deg[NN];
__device__ float g_dinv[NN];
__device__ int   g_rowptr[NN];
__device__ int   g_cursor[NN];
__device__ int   g_partials[64];
__device__ int   g_csrc[EE];

// ---------------- CSR build ------------------------------------------------
__global__ void zero_deg_kernel() {
    int i = blockIdx.x * blockDim.x + threadIdx.x;
    if (i < NN) g_deg[i] = 0;
}

__global__ void count_deg_kernel(const int* __restrict__ dst) {
    int e = blockIdx.x * blockDim.x + threadIdx.x;
    if (e < EE) atomicAdd(&g_deg[dst[e]], 1);
}

__global__ void dinv_kernel() {
    int i = blockIdx.x * blockDim.x + threadIdx.x;
    if (i < NN) g_dinv[i] = rsqrtf((float)g_deg[i] + 1.0f);
}

__global__ void scan_blocks_kernel() {
    __shared__ int sh[1024];
    int t = threadIdx.x;
    int i = blockIdx.x * 1024 + t;
    int v = (i < NN) ? g_deg[i] : 0;
    sh[t] = v;
    __syncthreads();
    #pragma unroll
    for (int off = 1; off < 1024; off <<= 1) {
        int add = (t >= off) ? sh[t - off] : 0;
        __syncthreads();
        sh[t] += add;
        __syncthreads();
    }
    if (i < NN) g_rowptr[i] = sh[t] - v;   // exclusive prefix
    if (t == 1023) g_partials[blockIdx.x] = sh[1023];
}

__global__ void scan_partials_kernel() {
    if (threadIdx.x == 0 && blockIdx.x == 0) {
        int acc = 0;
        for (int b = 0; b < NB; b++) {
            int t = g_partials[b];
            g_partials[b] = acc;
            acc += t;
        }
    }
}

__global__ void add_offsets_kernel() {
    int i = blockIdx.x * blockDim.x + threadIdx.x;
    if (i < NN) {
        int v = g_rowptr[i] + g_partials[i >> 10];
        g_rowptr[i] = v;
        g_cursor[i] = v;
    }
}

__global__ void fill_csr_kernel(const int* __restrict__ src, const int* __restrict__ dst) {
    int e = blockIdx.x * blockDim.x + threadIdx.x;
    if (e < EE) {
        int pos = atomicAdd(&g_cursor[dst[e]], 1);
        g_csrc[pos] = src[e];
    }
}

// ---------------- bf16 split conversions -----------------------------------
// A' layout: [M, 3K] with segments [Ahi | Ahi | Alo]
__global__ void conv_act_kernel(const float* __restrict__ in,
                                __nv_bfloat16* __restrict__ out, int M, int K) {
    int idx = blockIdx.x * blockDim.x + threadIdx.x;
    if (idx >= M * K) return;
    int m = idx / K;
    int k = idx - m * K;
    float x = in[idx];
    __nv_bfloat16 hi = __float2bfloat16(x);
    float lo = x - __bfloat162float(hi);
    __nv_bfloat16 loh = __float2bfloat16(lo);
    size_t base = (size_t)m * (3 * K);
    out[base + k]         = hi;
    out[base + K + k]     = hi;
    out[base + 2 * K + k] = loh;
}

// B' layout: [Npad, 3K] with segments [Bhi | Blo | Bhi]; rows >= Nr zero-filled
__global__ void conv_w_kernel(const float* __restrict__ in,
                              __nv_bfloat16* __restrict__ out,
                              int Nr, int Npad, int K) {
    int idx = blockIdx.x * blockDim.x + threadIdx.x;
    if (idx >= Npad * K) return;
    int n = idx / K;
    int k = idx - n * K;
    __nv_bfloat16 hi = __float2bfloat16(0.0f), loh = __float2bfloat16(0.0f);
    if (n < Nr) {
        float x = in[(size_t)n * K + k];
        hi = __float2bfloat16(x);
        float lo = x - __bfloat162float(hi);
        loh = __float2bfloat16(lo);
    }
    size_t base = (size_t)n * (3 * K);
    out[base + k]         = hi;
    out[base + K + k]     = loh;
    out[base + 2 * K + k] = hi;
}

// ---------------- tensor-core GEMM: C[M,N] = A'[M,Kp] * B'[N,Kp]^T ---------
#define GBM 128
#define GBN 128
#define GKT 32
#define KTP 40   // padded row stride in halves (conflict-free for ldmatrix)

__device__ __forceinline__ void ldmx4(uint32_t* r, const __nv_bfloat16* p) {
    uint32_t addr = (uint32_t)__cvta_generic_to_shared(p);
    asm volatile("ldmatrix.sync.aligned.m8n8.x4.shared.b16 {%0,%1,%2,%3}, [%4];"
                 : "=r"(r[0]), "=r"(r[1]), "=r"(r[2]), "=r"(r[3]) : "r"(addr));
}

__device__ __forceinline__ void mma16816(float* d, const uint32_t* a, const uint32_t* b) {
    asm volatile(
        "mma.sync.aligned.m16n8k16.row.col.f32.bf16.bf16.f32 "
        "{%0,%1,%2,%3}, {%4,%5,%6,%7}, {%8,%9}, {%0,%1,%2,%3};"
        : "+f"(d[0]), "+f"(d[1]), "+f"(d[2]), "+f"(d[3])
        : "r"(a[0]), "r"(a[1]), "r"(a[2]), "r"(a[3]), "r"(b[0]), "r"(b[1]));
}

__global__ __launch_bounds__(256, 2)
void mma_gemm_kernel(const __nv_bfloat16* __restrict__ A,
                     const __nv_bfloat16* __restrict__ B,
                     const float* __restrict__ bias, float* __restrict__ C,
                     int M, int Nreal, int Kp, int relu) {
    __shared__ __nv_bfloat16 As[GBM * KTP];
    __shared__ __nv_bfloat16 Bs[GBN * KTP];

    int tid = threadIdx.x;
    int bm = blockIdx.y * GBM;
    int bn = blockIdx.x * GBN;
    int wid = tid >> 5;
    int lane = tid & 31;
    int wm = wid >> 2;          // 0..1  (64-row warp slab)
    int wn = wid & 3;           // 0..3  (32-col warp slab)

    float acc[4][4][4];
    #pragma unroll
    for (int i = 0; i < 4; i++)
        #pragma unroll
        for (int j = 0; j < 4; j++)
            #pragma unroll
            for (int v = 0; v < 4; v++) acc[i][j][v] = 0.0f;

    for (int k0 = 0; k0 < Kp; k0 += GKT) {
        // load A tile: 128 rows x 32 halves = 512 uint4 over 256 threads (2 iters)
        #pragma unroll
        for (int it = 0; it < 2; it++) {
            int idx = tid + it * 256;
            int r = idx >> 2;
            int q = idx & 3;
            int m = bm + r;
            uint4 v = make_uint4(0u, 0u, 0u, 0u);
            if (m < M) v = *(const uint4*)&A[(size_t)m * Kp + k0 + q * 8];
            *(uint4*)&As[r * KTP + q * 8] = v;
        }
        // load B tile (rows always valid: B padded to multiple of 128)
        #pragma unroll
        for (int it = 0; it < 2; it++) {
            int idx = tid + it * 256;
            int r = idx >> 2;
            int q = idx & 3;
            uint4 v = *(const uint4*)&B[(size_t)(bn + r) * Kp + k0 + q * 8];
            *(uint4*)&Bs[r * KTP + q * 8] = v;
        }
        __syncthreads();

        #pragma unroll
        for (int ks = 0; ks < 2; ks++) {
            uint32_t afr[4][4];
            #pragma unroll
            for (int mi = 0; mi < 4; mi++) {
                int row = wm * 64 + mi * 16 + (lane & 15);
                int col = ks * 16 + (lane >> 4) * 8;
                ldmx4(afr[mi], &As[row * KTP + col]);
            }
            uint32_t bfr[2][4];
            #pragma unroll
            for (int pr = 0; pr < 2; pr++) {
                int row = wn * 32 + pr * 16 + (lane & 15);
                int col = ks * 16 + (lane >> 4) * 8;
                ldmx4(bfr[pr], &Bs[row * KTP + col]);
            }
            #pragma unroll
            for (int mi = 0; mi < 4; mi++) {
                #pragma unroll
                for (int ni = 0; ni < 4; ni++) {
                    // n-tile ni: pair = ni/2, half = ni%2 -> {b[half], b[half+2]}
                    uint32_t bb[2];
                    bb[0] = bfr[ni >> 1][ni & 1];
                    bb[1] = bfr[ni >> 1][(ni & 1) + 2];
                    mma16816(acc[mi][ni], afr[mi], bb);
                }
            }
        }
        __syncthreads();
    }

    // epilogue
    #pragma unroll
    for (int mi = 0; mi < 4; mi++) {
        #pragma unroll
        for (int ni = 0; ni < 4; ni++) {
            int row0 = bm + wm * 64 + mi * 16 + (lane >> 2);
            int col0 = bn + wn * 32 + ni * 8 + 2 * (lane & 3);
            if (col0 >= Nreal) continue;
            float bv0 = bias ? bias[col0] : 0.0f;
            float bv1 = bias ? bias[col0 + 1] : 0.0f;
            float v0 = acc[mi][ni][0] + bv0;
            float v1 = acc[mi][ni][1] + bv1;
            float v2 = acc[mi][ni][2] + bv0;
            float v3 = acc[mi][ni][3] + bv1;
            if (relu) {
                v0 = fmaxf(v0, 0.0f); v1 = fmaxf(v1, 0.0f);
                v2 = fmaxf(v2, 0.0f); v3 = fmaxf(v3, 0.0f);
            }
            if (row0 < M)     *(float2*)&C[(size_t)row0 * Nreal + col0] = make_float2(v0, v1);
            if (row0 + 8 < M) *(float2*)&C[(size_t)(row0 + 8) * Nreal + col0] = make_float2(v2, v3);
        }
    }
}

// ---------------- aggregation: block per node, CH channels -----------------
template<int CH>
__global__ __launch_bounds__(CH)
void aggregate_kernel(const float* __restrict__ h, const float* __restrict__ bias,
                      float* __restrict__ out) {
    int i = blockIdx.x;
    int c = threadIdx.x;
    __shared__ int   s_src[CH];
    __shared__ float s_w[CH];

    int start = g_rowptr[i];
    int d = g_deg[i];
    float di = g_dinv[i];
    float acc = 0.0f;

    for (int base = 0; base < d; base += CH) {
        int n = d - base;
        if (n > CH) n = CH;
        __syncthreads();
        if (c < n) {
            int s = g_csrc[start + base + c];
            s_src[c] = s;
            s_w[c] = g_dinv[s];
        }
        __syncthreads();
        #pragma unroll 4
        for (int j = 0; j < n; j++)
            acc += s_w[j] * h[(size_t)s_src[j] * CH + c];
    }

    float v = di * acc + di * di * h[(size_t)i * CH + c];
    if (bias) v += bias[c];
    out[(size_t)i * CH + c] = v;
}

// ---------------- launch ---------------------------------------------------
extern "C" void kernel_launch(void* const* d_in, const int* in_sizes, int n_in,
                              void* d_out, int out_size) {
    const float* x    = (const float*)d_in[0];
    const int*   ei   = (const int*)d_in[1];
    const float* W1   = (const float*)d_in[2];
    const float* b1   = (const float*)d_in[3];
    const float* W2   = (const float*)d_in[4];
    const float* b2   = (const float*)d_in[5];
    const float* Wout = (const float*)d_in[6];
    const float* bout = (const float*)d_in[7];
    float* out = (float*)d_out;

    const int* src = ei;         // edge_index[0]
    const int* dst = ei + EE;    // edge_index[1]

    float* bufA;  cudaGetSymbolAddress((void**)&bufA, g_bufA);
    float* bufB;  cudaGetSymbolAddress((void**)&bufB, g_bufB);
    __nv_bfloat16* a16;  cudaGetSymbolAddress((void**)&a16, g_a16);
    __nv_bfloat16* w16;  cudaGetSymbolAddress((void**)&w16, g_w16);

    // ---- CSR build ----
    zero_deg_kernel<<<(NN + 255) / 256, 256>>>();
    count_deg_kernel<<<(EE + 255) / 256, 256>>>(dst);
    dinv_kernel<<<(NN + 255) / 256, 256>>>();
    scan_blocks_kernel<<<NB, 1024>>>();
    scan_partials_kernel<<<1, 32>>>();
    add_offsets_kernel<<<(NN + 255) / 256, 256>>>();
    fill_csr_kernel<<<(EE + 255) / 256, 256>>>(src, dst);

    const int mblocks = (NN + GBM - 1) / GBM;   // 391

    // ---- layer 1: agg(x) -> bufA (F=128); bufB = relu(agg(x) @ W1^T + b1) ----
    aggregate_kernel<FF><<<NN, FF>>>(x, nullptr, bufA);
    conv_act_kernel<<<(NN * FF + 255) / 256, 256>>>(bufA, a16, NN, FF);
    conv_w_kernel<<<(HH * FF + 255) / 256, 256>>>(W1, w16, HH, HH, FF);
    {
        dim3 grid(HH / GBN, mblocks);
        mma_gemm_kernel<<<grid, 256>>>(a16, w16, b1, bufB, NN, HH, 3 * FF, 1);
    }

    // ---- layer 2: bufA = bufB @ W2^T ; agg2 + b2 -> bufB ----
    conv_act_kernel<<<(NN * HH + 255) / 256, 256>>>(bufB, a16, NN, HH);
    conv_w_kernel<<<(HH * HH + 255) / 256, 256>>>(W2, w16, HH, HH, HH);
    {
        dim3 grid(HH / GBN, mblocks);
        mma_gemm_kernel<<<grid, 256>>>(a16, w16, nullptr, bufA, NN, HH, 3 * HH, 0);
    }
    aggregate_kernel<HH><<<NN, HH>>>(bufA, b2, bufB);

    // ---- output: out = bufB @ Wout^T + bout (Wout padded to 128 rows) ----
    conv_act_kernel<<<(NN * HH + 255) / 256, 256>>>(bufB, a16, NN, HH);
    conv_w_kernel<<<(GBN * HH + 255) / 256, 256>>>(Wout, w16, CC, GBN, HH);
    {
        dim3 grid(1, mblocks);
        mma_gemm_kernel<<<grid, 256>>>(a16, w16, bout, out, NN, CC, 3 * HH, 0);
    }
}

// round 4
// speedup vs baseline: 3.5487x; 2.0392x over previous
#include <cuda_runtime.h>
#include <cuda_bf16.h>
#include <cstdint>

#define NN 50000
#define EE 800000
#define FF 128
#define HH 256
#define CC 40
#define NB ((NN + 1023) / 1024)   // 49 scan blocks

// ---------------- scratch (device globals; no runtime allocation) ----------
__device__ __nv_bfloat16 g_a16[(size_t)NN * 3 * FF];   // split agg(x)  [N, 384]
__device__ __nv_bfloat16 g_h16[(size_t)NN * 3 * HH];   // split relu(h1) [N, 768]
__device__ __nv_bfloat16 g_w16[(size_t)HH * 3 * FF];   // split W1 (256x384) / Wf (64x768)
__device__ float g_p[(size_t)NN * CC];                 // pre-agg logits [N, 40]
__device__ float g_wf32[CC * HH];                      // fused weight Wout@W2
__device__ float g_biasf[CC];                          // fused bias
__device__ int   g_deg[NN];
__device__ float g_dinv[NN];
__device__ int   g_rowptr[NN];
__device__ int   g_cursor[NN];
__device__ int   g_partials[64];
__device__ int   g_csrc[EE];

// ---------------- CSR build ------------------------------------------------
__global__ void zero_deg_kernel() {
    int i = blockIdx.x * blockDim.x + threadIdx.x;
    if (i < NN) g_deg[i] = 0;
}

__global__ void count_deg_kernel(const int* __restrict__ dst) {
    int e = blockIdx.x * blockDim.x + threadIdx.x;
    if (e < EE) atomicAdd(&g_deg[dst[e]], 1);
}

__global__ void dinv_kernel() {
    int i = blockIdx.x * blockDim.x + threadIdx.x;
    if (i < NN) g_dinv[i] = rsqrtf((float)g_deg[i] + 1.0f);
}

__global__ void scan_blocks_kernel() {
    __shared__ int sh[1024];
    int t = threadIdx.x;
    int i = blockIdx.x * 1024 + t;
    int v = (i < NN) ? g_deg[i] : 0;
    sh[t] = v;
    __syncthreads();
    #pragma unroll
    for (int off = 1; off < 1024; off <<= 1) {
        int add = (t >= off) ? sh[t - off] : 0;
        __syncthreads();
        sh[t] += add;
        __syncthreads();
    }
    if (i < NN) g_rowptr[i] = sh[t] - v;   // exclusive prefix
    if (t == 1023) g_partials[blockIdx.x] = sh[1023];
}

__global__ void scan_partials_kernel() {
    if (threadIdx.x == 0 && blockIdx.x == 0) {
        int acc = 0;
        for (int b = 0; b < NB; b++) {
            int t = g_partials[b];
            g_partials[b] = acc;
            acc += t;
        }
    }
}

__global__ void add_offsets_kernel() {
    int i = blockIdx.x * blockDim.x + threadIdx.x;
    if (i < NN) {
        int v = g_rowptr[i] + g_partials[i >> 10];
        g_rowptr[i] = v;
        g_cursor[i] = v;
    }
}

__global__ void fill_csr_kernel(const int* __restrict__ src, const int* __restrict__ dst) {
    int e = blockIdx.x * blockDim.x + threadIdx.x;
    if (e < EE) {
        int pos = atomicAdd(&g_cursor[dst[e]], 1);
        g_csrc[pos] = src[e];
    }
}

// ---------------- weight split: B' = [Bhi | Blo | Bhi] over K ---------------
__global__ void conv_w_kernel(const float* __restrict__ in,
                              __nv_bfloat16* __restrict__ out,
                              int Nr, int Npad, int K) {
    int idx = blockIdx.x * blockDim.x + threadIdx.x;
    if (idx >= Npad * K) return;
    int n = idx / K;
    int k = idx - n * K;
    __nv_bfloat16 hi = __float2bfloat16(0.0f), loh = __float2bfloat16(0.0f);
    if (n < Nr) {
        float x = in[(size_t)n * K + k];
        hi = __float2bfloat16(x);
        float lo = x - __bfloat162float(hi);
        loh = __float2bfloat16(lo);
    }
    size_t base = (size_t)n * (3 * K);
    out[base + k]         = hi;
    out[base + K + k]     = loh;
    out[base + 2 * K + k] = hi;
}

// ---------------- fused weight: Wf = Wout @ W2; biasf = bout + Wout@b2 ------
__global__ void fuse_w_kernel(const float* __restrict__ Wout, const float* __restrict__ W2,
                              const float* __restrict__ b2, const float* __restrict__ bout) {
    __shared__ float sh[256];
    int c = blockIdx.x;          // 0..39
    int i = threadIdx.x;         // 0..255
    float acc = 0.0f;
    #pragma unroll 4
    for (int o = 0; o < HH; o++)
        acc += Wout[c * HH + o] * W2[(size_t)o * HH + i];
    g_wf32[c * HH + i] = acc;
    // bias reduction
    sh[i] = Wout[c * HH + i] * b2[i];
    __syncthreads();
    for (int off = 128; off > 0; off >>= 1) {
        if (i < off) sh[i] += sh[i + off];
        __syncthreads();
    }
    if (i == 0) g_biasf[c] = bout[c] + sh[0];
}

// ---------------- agg(x) with split-bf16 output -----------------------------
// block per node, 128 threads (F channels); out layout [hi(128)|hi(128)|lo(128)]
__global__ __launch_bounds__(FF)
void aggregate_split_kernel(const float* __restrict__ h) {
    int i = blockIdx.x;
    int c = threadIdx.x;
    __shared__ int   s_src[FF];
    __shared__ float s_w[FF];

    int start = g_rowptr[i];
    int d = g_deg[i];
    float di = g_dinv[i];
    float acc = 0.0f;

    for (int base = 0; base < d; base += FF) {
        int n = d - base;
        if (n > FF) n = FF;
        __syncthreads();
        if (c < n) {
            int s = g_csrc[start + base + c];
            s_src[c] = s;
            s_w[c] = g_dinv[s];
        }
        __syncthreads();
        #pragma unroll 4
        for (int j = 0; j < n; j++)
            acc += s_w[j] * h[(size_t)s_src[j] * FF + c];
    }

    float v = di * acc + di * di * h[(size_t)i * FF + c];
    __nv_bfloat16 hi = __float2bfloat16(v);
    __nv_bfloat16 lo = __float2bfloat16(v - __bfloat162float(hi));
    size_t b = (size_t)i * (3 * FF);
    g_a16[b + c]          = hi;
    g_a16[b + FF + c]     = hi;
    g_a16[b + 2 * FF + c] = lo;
}

// ---------------- tensor-core GEMM ------------------------------------------
#define GKT 32
#define KTP 40   // padded SMEM row stride (halves), conflict-free for ldmatrix

__device__ __forceinline__ void ldmx4(uint32_t* r, const __nv_bfloat16* p) {
    uint32_t addr = (uint32_t)__cvta_generic_to_shared(p);
    asm volatile("ldmatrix.sync.aligned.m8n8.x4.shared.b16 {%0,%1,%2,%3}, [%4];"
                 : "=r"(r[0]), "=r"(r[1]), "=r"(r[2]), "=r"(r[3]) : "r"(addr));
}

__device__ __forceinline__ void mma16816(float* d, const uint32_t* a, const uint32_t* b) {
    asm volatile(
        "mma.sync.aligned.m16n8k16.row.col.f32.bf16.bf16.f32 "
        "{%0,%1,%2,%3}, {%4,%5,%6,%7}, {%8,%9}, {%0,%1,%2,%3};"
        : "+f"(d[0]), "+f"(d[1]), "+f"(d[2]), "+f"(d[3])
        : "r"(a[0]), "r"(a[1]), "r"(a[2]), "r"(a[3]), "r"(b[0]), "r"(b[1]));
}

// C[M,N] = A'[M,Kp] * B'[N,Kp]^T. BM=128 rows; warp grid WR x WC;
// warp tile = (MI*16) x (NI*8). SPLIT_OUT: write bf16 [hi|hi|lo] rows (stride 3N)
// with bias+relu; else fp32 with bias(+relu).
template<int BN, int WR, int WC, int MI, int NI, int SPLIT_OUT>
__global__ __launch_bounds__(256, 2)
void mma_gemm_kernel(const __nv_bfloat16* __restrict__ A,
                     const __nv_bfloat16* __restrict__ B,
                     const float* __restrict__ bias,
                     float* __restrict__ Cf, __nv_bfloat16* __restrict__ Cs,
                     int M, int Nreal, int Kp, int relu) {
    __shared__ __nv_bfloat16 As[128 * KTP];
    __shared__ __nv_bfloat16 Bs[BN * KTP];

    int tid = threadIdx.x;
    int bm = blockIdx.y * 128;
    int bn = blockIdx.x * BN;
    int wid = tid >> 5;
    int lane = tid & 31;
    int wm = wid / WC;
    int wn = wid % WC;

    float acc[MI][NI][4];
    #pragma unroll
    for (int i = 0; i < MI; i++)
        #pragma unroll
        for (int j = 0; j < NI; j++)
            #pragma unroll
            for (int v = 0; v < 4; v++) acc[i][j][v] = 0.0f;

    for (int k0 = 0; k0 < Kp; k0 += GKT) {
        // A tile: 128 rows x 32 halves -> 512 uint4 over 256 threads
        #pragma unroll
        for (int it = 0; it < 2; it++) {
            int idx = tid + it * 256;
            int r = idx >> 2;
            int q = idx & 3;
            int m = bm + r;
            uint4 v = make_uint4(0u, 0u, 0u, 0u);
            if (m < M) v = *(const uint4*)&A[(size_t)m * Kp + k0 + q * 8];
            *(uint4*)&As[r * KTP + q * 8] = v;
        }
        // B tile (rows always valid: padded)
        #pragma unroll
        for (int idx = tid; idx < BN * 4; idx += 256) {
            int r = idx >> 2;
            int q = idx & 3;
            uint4 v = *(const uint4*)&B[(size_t)(bn + r) * Kp + k0 + q * 8];
            *(uint4*)&Bs[r * KTP + q * 8] = v;
        }
        __syncthreads();

        #pragma unroll
        for (int ks = 0; ks < 2; ks++) {
            uint32_t afr[MI][4];
            #pragma unroll
            for (int mi = 0; mi < MI; mi++) {
                int row = wm * (MI * 16) + mi * 16 + (lane & 15);
                int col = ks * 16 + (lane >> 4) * 8;
                ldmx4(afr[mi], &As[row * KTP + col]);
            }
            uint32_t bfr[NI / 2][4];
            #pragma unroll
            for (int pr = 0; pr < NI / 2; pr++) {
                int row = wn * (NI * 8) + pr * 16 + (lane & 15);
                int col = ks * 16 + (lane >> 4) * 8;
                ldmx4(bfr[pr], &Bs[row * KTP + col]);
            }
            #pragma unroll
            for (int mi = 0; mi < MI; mi++) {
                #pragma unroll
                for (int ni = 0; ni < NI; ni++) {
                    uint32_t bb[2];
                    bb[0] = bfr[ni >> 1][ni & 1];
                    bb[1] = bfr[ni >> 1][(ni & 1) + 2];
                    mma16816(acc[mi][ni], afr[mi], bb);
                }
            }
        }
        __syncthreads();
    }

    // epilogue
    #pragma unroll
    for (int mi = 0; mi < MI; mi++) {
        #pragma unroll
        for (int ni = 0; ni < NI; ni++) {
            int row0 = bm + wm * (MI * 16) + mi * 16 + (lane >> 2);
            int col0 = bn + wn * (NI * 8) + ni * 8 + 2 * (lane & 3);
            if (col0 >= Nreal) continue;
            float bv0 = bias ? bias[col0] : 0.0f;
            float bv1 = bias ? bias[col0 + 1] : 0.0f;
            float v0 = acc[mi][ni][0] + bv0;
            float v1 = acc[mi][ni][1] + bv1;
            float v2 = acc[mi][ni][2] + bv0;
            float v3 = acc[mi][ni][3] + bv1;
            if (relu) {
                v0 = fmaxf(v0, 0.0f); v1 = fmaxf(v1, 0.0f);
                v2 = fmaxf(v2, 0.0f); v3 = fmaxf(v3, 0.0f);
            }
            if (SPLIT_OUT) {
                int S = 3 * Nreal;
                #pragma unroll
                for (int half = 0; half < 2; half++) {
                    int row = row0 + half * 8;
                    if (row >= M) continue;
                    float a0 = half ? v2 : v0;
                    float a1 = half ? v3 : v1;
                    __nv_bfloat16 h0 = __float2bfloat16(a0);
                    __nv_bfloat16 h1 = __float2bfloat16(a1);
                    __nv_bfloat162 hip; hip.x = h0; hip.y = h1;
                    __nv_bfloat162 lop;
                    lop.x = __float2bfloat16(a0 - __bfloat162float(h0));
                    lop.y = __float2bfloat16(a1 - __bfloat162float(h1));
                    size_t base = (size_t)row * S + col0;
                    *(__nv_bfloat162*)&Cs[base]             = hip;
                    *(__nv_bfloat162*)&Cs[base + Nreal]     = hip;
                    *(__nv_bfloat162*)&Cs[base + 2 * Nreal] = lop;
                }
            } else {
                if (row0 < M)     *(float2*)&Cf[(size_t)row0 * Nreal + col0] = make_float2(v0, v1);
                if (row0 + 8 < M) *(float2*)&Cf[(size_t)(row0 + 8) * Nreal + col0] = make_float2(v2, v3);
            }
        }
    }
}

// ---------------- final aggregation at C=40: warp per node ------------------
__global__ __launch_bounds__(256)
void aggregate_final_kernel(float* __restrict__ out) {
    int node = blockIdx.x * 8 + (threadIdx.x >> 5);
    int lane = threadIdx.x & 31;
    if (node >= NN) return;

    const float* __restrict__ p = g_p;
    int start = g_rowptr[node];
    int d = g_deg[node];
    float di = g_dinv[node];

    float acc0 = 0.0f, acc1 = 0.0f;
    #pragma unroll 4
    for (int j = 0; j < d; j++) {
        int s = g_csrc[start + j];        // uniform across warp -> broadcast
        float w = g_dinv[s];
        const float* row = &p[(size_t)s * CC];
        acc0 += w * row[lane];
        if (lane < CC - 32) acc1 += w * row[32 + lane];
    }

    const float* self = &p[(size_t)node * CC];
    float v0 = di * acc0 + di * di * self[lane] + g_biasf[lane];
    out[(size_t)node * CC + lane] = v0;
    if (lane < CC - 32) {
        float v1 = di * acc1 + di * di * self[32 + lane] + g_biasf[32 + lane];
        out[(size_t)node * CC + 32 + lane] = v1;
    }
}

// ---------------- launch ----------------------------------------------------
extern "C" void kernel_launch(void* const* d_in, const int* in_sizes, int n_in,
                              void* d_out, int out_size) {
    const float* x    = (const float*)d_in[0];
    const int*   ei   = (const int*)d_in[1];
    const float* W1   = (const float*)d_in[2];
    const float* b1   = (const float*)d_in[3];
    const float* W2   = (const float*)d_in[4];
    const float* b2   = (const float*)d_in[5];
    const float* Wout = (const float*)d_in[6];
    const float* bout = (const float*)d_in[7];
    float* out = (float*)d_out;

    const int* src = ei;         // edge_index[0]
    const int* dst = ei + EE;    // edge_index[1]

    __nv_bfloat16* a16;  cudaGetSymbolAddress((void**)&a16, g_a16);
    __nv_bfloat16* h16;  cudaGetSymbolAddress((void**)&h16, g_h16);
    __nv_bfloat16* w16;  cudaGetSymbolAddress((void**)&w16, g_w16);
    float* pbuf; cudaGetSymbolAddress((void**)&pbuf, g_p);
    float* wf32; cudaGetSymbolAddress((void**)&wf32, g_wf32);

    // ---- CSR build ----
    zero_deg_kernel<<<(NN + 255) / 256, 256>>>();
    count_deg_kernel<<<(EE + 255) / 256, 256>>>(dst);
    dinv_kernel<<<(NN + 255) / 256, 256>>>();
    scan_blocks_kernel<<<NB, 1024>>>();
    scan_partials_kernel<<<1, 32>>>();
    add_offsets_kernel<<<(NN + 255) / 256, 256>>>();
    fill_csr_kernel<<<(EE + 255) / 256, 256>>>(src, dst);

    const int mblocks = (NN + 127) / 128;   // 391

    // ---- W1 split (independent of agg) ----
    conv_w_kernel<<<(HH * FF + 255) / 256, 256>>>(W1, w16, HH, HH, FF);

    // ---- agg(x) -> split a16 [N, 384] ----
    aggregate_split_kernel<<<NN, FF>>>(x);

    // ---- GEMM1: h16 = split(relu(a16 @ W1'^T + b1))  [N, 768] ----
    {
        dim3 grid(HH / 128, mblocks);
        mma_gemm_kernel<128, 2, 4, 4, 4, 1><<<grid, 256>>>(
            a16, w16, b1, nullptr, h16, NN, HH, 3 * FF, 1);
    }

    // ---- fused weight: Wf = Wout@W2 (fp32), biasf = bout + Wout@b2 ----
    fuse_w_kernel<<<CC, 256>>>(Wout, W2, b2, bout);
    conv_w_kernel<<<(64 * HH + 255) / 256, 256>>>(wf32, w16, CC, 64, HH);

    // ---- fused GEMM: p = h16 @ Wf'^T  [N, 40] fp32 ----
    {
        dim3 grid(1, mblocks);
        mma_gemm_kernel<64, 4, 2, 2, 4, 0><<<grid, 256>>>(
            h16, w16, nullptr, pbuf, nullptr, NN, CC, 3 * HH, 0);
    }

    // ---- final aggregation at C=40 -> out ----
    aggregate_final_kernel<<<(NN + 7) / 8, 256>>>(out);
}

// round 5
// speedup vs baseline: 3.7832x; 1.0661x over previous
#include <cuda_runtime.h>
#include <cuda_bf16.h>
#include <cstdint>

#define NN 50000
#define EE 800000
#define FF 128
#define HH 256
#define CC 40
#define NB ((NN + 1023) / 1024)   // 49 scan blocks

// ---------------- scratch (device globals; no runtime allocation) ----------
__device__ __nv_bfloat16 g_a16[(size_t)NN * 2 * FF];   // split agg(x)  [N, 256] = [hi|lo]
__device__ __nv_bfloat16 g_h16[(size_t)NN * 2 * HH];   // split relu(h1) [N, 512] = [hi|lo]
__device__ __nv_bfloat16 g_w16[(size_t)HH * 2 * HH];   // split W1 (256x256) / Wf (64x512)
__device__ float g_p[(size_t)NN * CC];                 // pre-agg logits [N, 40]
__device__ float g_wf32[CC * HH];                      // fused weight Wout@W2
__device__ float g_biasf[CC];                          // fused bias
__device__ int   g_deg[NN];
__device__ float g_dinv[NN];
__device__ int   g_rowptr[NN];
__device__ int   g_cursor[NN];
__device__ int   g_partials[64];
__device__ int   g_csrc[EE];
__device__ float g_cw[EE];                             // per-edge dinv[src]

// ---------------- CSR build ------------------------------------------------
__global__ void zero_deg_kernel() {
    int i = blockIdx.x * blockDim.x + threadIdx.x;
    if (i < NN) g_deg[i] = 0;
}

__global__ void count_deg_kernel(const int* __restrict__ dst) {
    int e = blockIdx.x * blockDim.x + threadIdx.x;
    if (e < EE) atomicAdd(&g_deg[dst[e]], 1);
}

__global__ void dinv_kernel() {
    int i = blockIdx.x * blockDim.x + threadIdx.x;
    if (i < NN) g_dinv[i] = rsqrtf((float)g_deg[i] + 1.0f);
}

__global__ void scan_blocks_kernel() {
    __shared__ int sh[1024];
    int t = threadIdx.x;
    int i = blockIdx.x * 1024 + t;
    int v = (i < NN) ? g_deg[i] : 0;
    sh[t] = v;
    __syncthreads();
    #pragma unroll
    for (int off = 1; off < 1024; off <<= 1) {
        int add = (t >= off) ? sh[t - off] : 0;
        __syncthreads();
        sh[t] += add;
        __syncthreads();
    }
    if (i < NN) g_rowptr[i] = sh[t] - v;   // exclusive prefix
    if (t == 1023) g_partials[blockIdx.x] = sh[1023];
}

__global__ void scan_partials_kernel() {
    if (threadIdx.x == 0 && blockIdx.x == 0) {
        int acc = 0;
        for (int b = 0; b < NB; b++) {
            int t = g_partials[b];
            g_partials[b] = acc;
            acc += t;
        }
    }
}

__global__ void add_offsets_kernel() {
    int i = blockIdx.x * blockDim.x + threadIdx.x;
    if (i < NN) {
        int v = g_rowptr[i] + g_partials[i >> 10];
        g_rowptr[i] = v;
        g_cursor[i] = v;
    }
}

__global__ void fill_csr_kernel(const int* __restrict__ src, const int* __restrict__ dst) {
    int e = blockIdx.x * blockDim.x + threadIdx.x;
    if (e < EE) {
        int s = src[e];
        int pos = atomicAdd(&g_cursor[dst[e]], 1);
        g_csrc[pos] = s;
        g_cw[pos] = g_dinv[s];
    }
}

// ---------------- weight split: out[n] = [hi(K) | lo(K)] -------------------
__global__ void conv_w_kernel(const float* __restrict__ in,
                              __nv_bfloat16* __restrict__ out,
                              int Nr, int Npad, int K) {
    int idx = blockIdx.x * blockDim.x + threadIdx.x;
    if (idx >= Npad * K) return;
    int n = idx / K;
    int k = idx - n * K;
    __nv_bfloat16 hi = __float2bfloat16(0.0f), loh = __float2bfloat16(0.0f);
    if (n < Nr) {
        float x = in[(size_t)n * K + k];
        hi = __float2bfloat16(x);
        float lo = x - __bfloat162float(hi);
        loh = __float2bfloat16(lo);
    }
    size_t base = (size_t)n * (2 * K);
    out[base + k]     = hi;
    out[base + K + k] = loh;
}

// ---------------- fused weight: Wf = Wout @ W2; biasf = bout + Wout@b2 ------
__global__ void fuse_w_kernel(const float* __restrict__ Wout, const float* __restrict__ W2,
                              const float* __restrict__ b2, const float* __restrict__ bout) {
    __shared__ float sh[256];
    int c = blockIdx.x;          // 0..39
    int i = threadIdx.x;         // 0..255
    float acc = 0.0f;
    #pragma unroll 4
    for (int o = 0; o < HH; o++)
        acc += Wout[c * HH + o] * W2[(size_t)o * HH + i];
    g_wf32[c * HH + i] = acc;
    // bias reduction
    sh[i] = Wout[c * HH + i] * b2[i];
    __syncthreads();
    for (int off = 128; off > 0; off >>= 1) {
        if (i < off) sh[i] += sh[i + off];
        __syncthreads();
    }
    if (i == 0) g_biasf[c] = bout[c] + sh[0];
}

// ---------------- agg(x) with split-bf16 output -----------------------------
// block per node, 128 threads; out layout [hi(128)|lo(128)]
__global__ __launch_bounds__(FF)
void aggregate_split_kernel(const float* __restrict__ h) {
    int i = blockIdx.x;
    int c = threadIdx.x;
    __shared__ int   s_src[FF];
    __shared__ float s_w[FF];

    int start = g_rowptr[i];
    int d = g_deg[i];
    float di = g_dinv[i];
    float acc = 0.0f;

    if (d <= FF) {
        // fast path: one chunk
        if (c < d) {
            s_src[c] = g_csrc[start + c];
            s_w[c] = g_cw[start + c];
        }
        __syncthreads();
        #pragma unroll 4
        for (int j = 0; j < d; j++)
            acc += s_w[j] * h[(size_t)s_src[j] * FF + c];
    } else {
        for (int base = 0; base < d; base += FF) {
            int n = d - base;
            if (n > FF) n = FF;
            __syncthreads();
            if (c < n) {
                s_src[c] = g_csrc[start + base + c];
                s_w[c] = g_cw[start + base + c];
            }
            __syncthreads();
            #pragma unroll 4
            for (int j = 0; j < n; j++)
                acc += s_w[j] * h[(size_t)s_src[j] * FF + c];
        }
    }

    float v = di * acc + di * di * h[(size_t)i * FF + c];
    __nv_bfloat16 hi = __float2bfloat16(v);
    __nv_bfloat16 lo = __float2bfloat16(v - __bfloat162float(hi));
    size_t b = (size_t)i * (2 * FF);
    g_a16[b + c]      = hi;
    g_a16[b + FF + c] = lo;
}

// ---------------- tensor-core GEMM ------------------------------------------
#define GKT 32
#define KTP 40   // padded SMEM row stride (halves), conflict-free for ldmatrix

__device__ __forceinline__ void ldmx4(uint32_t* r, const __nv_bfloat16* p) {
    uint32_t addr = (uint32_t)__cvta_generic_to_shared(p);
    asm volatile("ldmatrix.sync.aligned.m8n8.x4.shared.b16 {%0,%1,%2,%3}, [%4];"
                 : "=r"(r[0]), "=r"(r[1]), "=r"(r[2]), "=r"(r[3]) : "r"(addr));
}

__device__ __forceinline__ void mma16816(float* d, const uint32_t* a, const uint32_t* b) {
    asm volatile(
        "mma.sync.aligned.m16n8k16.row.col.f32.bf16.bf16.f32 "
        "{%0,%1,%2,%3}, {%4,%5,%6,%7}, {%8,%9}, {%0,%1,%2,%3};"
        : "+f"(d[0]), "+f"(d[1]), "+f"(d[2]), "+f"(d[3])
        : "r"(a[0]), "r"(a[1]), "r"(a[2]), "r"(a[3]), "r"(b[0]), "r"(b[1]));
}

// Logical C[M,N] = A'[M,3K] * B'[N,3K]^T where A' = [Ahi|Ahi|Alo],
// B' = [Bhi|Blo|Bhi], but A and B are stored compactly as [hi|lo] with
// row stride 2K. Segment s of the logical K axis maps to stored offsets:
//   A: s0->hi, s1->hi, s2->lo      B: s0->hi, s1->lo, s2->hi
// BM=128 rows; warp tile = (MI*16) x (NI*8), warp grid (8/WC) x WC.
// SPLIT_OUT: write bf16 [hi|lo] rows (stride 2N) with bias+relu; else fp32.
template<int BN, int WC, int MI, int NI, int SPLIT_OUT>
__global__ __launch_bounds__(256, 2)
void mma_gemm_kernel(const __nv_bfloat16* __restrict__ A,
                     const __nv_bfloat16* __restrict__ B,
                     const float* __restrict__ bias,
                     float* __restrict__ Cf, __nv_bfloat16* __restrict__ Cs,
                     int M, int Nreal, int K, int relu) {
    __shared__ __nv_bfloat16 As[128 * KTP];
    __shared__ __nv_bfloat16 Bs[BN * KTP];

    int tid = threadIdx.x;
    int bm = blockIdx.y * 128;
    int bn = blockIdx.x * BN;
    int wid = tid >> 5;
    int lane = tid & 31;
    int wm = wid / WC;
    int wn = wid % WC;
    int strideAB = 2 * K;

    float acc[MI][NI][4];
    #pragma unroll
    for (int i = 0; i < MI; i++)
        #pragma unroll
        for (int j = 0; j < NI; j++)
            #pragma unroll
            for (int v = 0; v < 4; v++) acc[i][j][v] = 0.0f;

    int Kp = 3 * K;
    for (int k0 = 0; k0 < Kp; k0 += GKT) {
        int seg = k0 / K;
        int kk = k0 - seg * K;
        int aoff = (seg == 2 ? K : 0) + kk;
        int boff = (seg == 1 ? K : 0) + kk;

        // A tile: 128 rows x 32 halves -> 512 uint4 over 256 threads
        #pragma unroll
        for (int it = 0; it < 2; it++) {
            int idx = tid + it * 256;
            int r = idx >> 2;
            int q = idx & 3;
            int m = bm + r;
            uint4 v = make_uint4(0u, 0u, 0u, 0u);
            if (m < M) v = *(const uint4*)&A[(size_t)m * strideAB + aoff + q * 8];
            *(uint4*)&As[r * KTP + q * 8] = v;
        }
        // B tile (rows always valid: padded)
        #pragma unroll
        for (int idx = tid; idx < BN * 4; idx += 256) {
            int r = idx >> 2;
            int q = idx & 3;
            uint4 v = *(const uint4*)&B[(size_t)(bn + r) * strideAB + boff + q * 8];
            *(uint4*)&Bs[r * KTP + q * 8] = v;
        }
        __syncthreads();

        #pragma unroll
        for (int ks = 0; ks < 2; ks++) {
            uint32_t afr[MI][4];
            #pragma unroll
            for (int mi = 0; mi < MI; mi++) {
                int row = wm * (MI * 16) + mi * 16 + (lane & 15);
                int col = ks * 16 + (lane >> 4) * 8;
                ldmx4(afr[mi], &As[row * KTP + col]);
            }
            uint32_t bfr[NI / 2][4];
            #pragma unroll
            for (int pr = 0; pr < NI / 2; pr++) {
                int row = wn * (NI * 8) + pr * 16 + (lane & 15);
                int col = ks * 16 + (lane >> 4) * 8;
                ldmx4(bfr[pr], &Bs[row * KTP + col]);
            }
            #pragma unroll
            for (int mi = 0; mi < MI; mi++) {
                #pragma unroll
                for (int ni = 0; ni < NI; ni++) {
                    uint32_t bb[2];
                    bb[0] = bfr[ni >> 1][ni & 1];
                    bb[1] = bfr[ni >> 1][(ni & 1) + 2];
                    mma16816(acc[mi][ni], afr[mi], bb);
                }
            }
        }
        __syncthreads();
    }

    // epilogue
    #pragma unroll
    for (int mi = 0; mi < MI; mi++) {
        #pragma unroll
        for (int ni = 0; ni < NI; ni++) {
            int row0 = bm + wm * (MI * 16) + mi * 16 + (lane >> 2);
            int col0 = bn + wn * (NI * 8) + ni * 8 + 2 * (lane & 3);
            if (col0 >= Nreal) continue;
            float bv0 = bias ? bias[col0] : 0.0f;
            float bv1 = bias ? bias[col0 + 1] : 0.0f;
            float v0 = acc[mi][ni][0] + bv0;
            float v1 = acc[mi][ni][1] + bv1;
            float v2 = acc[mi][ni][2] + bv0;
            float v3 = acc[mi][ni][3] + bv1;
            if (relu) {
                v0 = fmaxf(v0, 0.0f); v1 = fmaxf(v1, 0.0f);
                v2 = fmaxf(v2, 0.0f); v3 = fmaxf(v3, 0.0f);
            }
            if (SPLIT_OUT) {
                int S = 2 * Nreal;
                #pragma unroll
                for (int half = 0; half < 2; half++) {
                    int row = row0 + half * 8;
                    if (row >= M) continue;
                    float a0 = half ? v2 : v0;
                    float a1 = half ? v3 : v1;
                    __nv_bfloat16 h0 = __float2bfloat16(a0);
                    __nv_bfloat16 h1 = __float2bfloat16(a1);
                    __nv_bfloat162 hip; hip.x = h0; hip.y = h1;
                    __nv_bfloat162 lop;
                    lop.x = __float2bfloat16(a0 - __bfloat162float(h0));
                    lop.y = __float2bfloat16(a1 - __bfloat162float(h1));
                    size_t base = (size_t)row * S + col0;
                    *(__nv_bfloat162*)&Cs[base]         = hip;
                    *(__nv_bfloat162*)&Cs[base + Nreal] = lop;
                }
            } else {
                if (row0 < M)     *(float2*)&Cf[(size_t)row0 * Nreal + col0] = make_float2(v0, v1);
                if (row0 + 8 < M) *(float2*)&Cf[(size_t)(row0 + 8) * Nreal + col0] = make_float2(v2, v3);
            }
        }
    }
}

// ---------------- final aggregation at C=40: warp per node ------------------
__global__ __launch_bounds__(256)
void aggregate_final_kernel(float* __restrict__ out) {
    int node = blockIdx.x * 8 + (threadIdx.x >> 5);
    int lane = threadIdx.x & 31;
    if (node >= NN) return;

    const float* __restrict__ p = g_p;
    int start = g_rowptr[node];
    int d = g_deg[node];
    float di = g_dinv[node];

    float acc0 = 0.0f, acc1 = 0.0f;
    #pragma unroll 4
    for (int j = 0; j < d; j++) {
        int s = g_csrc[start + j];        // uniform across warp -> broadcast
        float w = g_cw[start + j];
        const float* row = &p[(size_t)s * CC];
        acc0 += w * row[lane];
        if (lane < CC - 32) acc1 += w * row[32 + lane];
    }

    const float* self = &p[(size_t)node * CC];
    float v0 = di * acc0 + di * di * self[lane] + g_biasf[lane];
    out[(size_t)node * CC + lane] = v0;
    if (lane < CC - 32) {
        float v1 = di * acc1 + di * di * self[32 + lane] + g_biasf[32 + lane];
        out[(size_t)node * CC + 32 + lane] = v1;
    }
}

// ---------------- launch ----------------------------------------------------
extern "C" void kernel_launch(void* const* d_in, const int* in_sizes, int n_in,
                              void* d_out, int out_size) {
    const float* x    = (const float*)d_in[0];
    const int*   ei   = (const int*)d_in[1];
    const float* W1   = (const float*)d_in[2];
    const float* b1   = (const float*)d_in[3];
    const float* W2   = (const float*)d_in[4];
    const float* b2   = (const float*)d_in[5];
    const float* Wout = (const float*)d_in[6];
    const float* bout = (const float*)d_in[7];
    float* out = (float*)d_out;

    const int* src = ei;         // edge_index[0]
    const int* dst = ei + EE;    // edge_index[1]

    __nv_bfloat16* a16;  cudaGetSymbolAddress((void**)&a16, g_a16);
    __nv_bfloat16* h16;  cudaGetSymbolAddress((void**)&h16, g_h16);
    __nv_bfloat16* w16;  cudaGetSymbolAddress((void**)&w16, g_w16);
    float* pbuf; cudaGetSymbolAddress((void**)&pbuf, g_p);
    float* wf32; cudaGetSymbolAddress((void**)&wf32, g_wf32);

    // ---- CSR build ----
    zero_deg_kernel<<<(NN + 255) / 256, 256>>>();
    count_deg_kernel<<<(EE + 255) / 256, 256>>>(dst);
    dinv_kernel<<<(NN + 255) / 256, 256>>>();
    scan_blocks_kernel<<<NB, 1024>>>();
    scan_partials_kernel<<<1, 32>>>();
    add_offsets_kernel<<<(NN + 255) / 256, 256>>>();
    fill_csr_kernel<<<(EE + 255) / 256, 256>>>(src, dst);

    const int mblocks = (NN + 127) / 128;   // 391

    // ---- W1 split (independent of agg) ----
    conv_w_kernel<<<(HH * FF + 255) / 256, 256>>>(W1, w16, HH, HH, FF);

    // ---- agg(x) -> split a16 [N, 256] = [hi|lo] ----
    aggregate_split_kernel<<<NN, FF>>>(x);

    // ---- GEMM1: h16 = split(relu(a16 @ W1'^T + b1))  [N, 512] = [hi|lo] ----
    {
        dim3 grid(HH / 128, mblocks);
        mma_gemm_kernel<128, 4, 4, 4, 1><<<grid, 256>>>(
            a16, w16, b1, nullptr, h16, NN, HH, FF, 1);
    }

    // ---- fused weight: Wf = Wout@W2 (fp32), biasf = bout + Wout@b2 ----
    fuse_w_kernel<<<CC, 256>>>(Wout, W2, b2, bout);
    conv_w_kernel<<<(64 * HH + 255) / 256, 256>>>(wf32, w16, CC, 64, HH);

    // ---- fused GEMM: p = h16 @ Wf'^T  [N, 40] fp32 ----
    {
        dim3 grid(1, mblocks);
        mma_gemm_kernel<64, 2, 2, 4, 0><<<grid, 256>>>(
            h16, w16, nullptr, pbuf, nullptr, NN, CC, HH, 0);
    }

    // ---- final aggregation at C=40 -> out ----
    aggregate_final_kernel<<<(NN + 7) / 8, 256>>>(out);
}

// round 8
// speedup vs baseline: 4.1822x; 1.1055x over previous
#include <cuda_runtime.h>
#include <cuda_bf16.h>
#include <cstdint>

#define NN 50000
#define EE 800000
#define FF 128
#define HH 256
#define CC 40
#define PSTR 64                   // padded p row stride
#define NB ((NN + 1023) / 1024)   // 49 scan blocks

// ---------------- scratch (device globals; no runtime allocation) ----------
__device__ __nv_bfloat16 g_a16[(size_t)NN * 2 * FF];   // split agg(x)  [N,256]=[hi|lo]
__device__ __nv_bfloat16 g_w16[(size_t)HH * 2 * FF];   // split W1 [256][hi128|lo128]
__device__ __nv_bfloat16 g_wf16[(size_t)64 * 2 * HH];  // split Wf [64][hi256|lo256]
__device__ float g_p[(size_t)NN * PSTR];               // pre-agg logits [N,40] pad 64
__device__ float g_wf32[CC * HH];                      // fused weight Wout@W2
__device__ float g_biasf[CC];                          // fused bias
__device__ int   g_deg[NN];
__device__ float g_dinv[NN];
__device__ int   g_rowptr[NN];
__device__ int   g_cursor[NN];
__device__ int   g_partials[64];
__device__ int   g_csrc[EE];
__device__ float g_cw[EE];                             // per-edge dinv[src]

// ---------------- CSR build ------------------------------------------------
__global__ void zero_deg_kernel() {
    int i = blockIdx.x * blockDim.x + threadIdx.x;
    if (i < NN) g_deg[i] = 0;
}

__global__ void count_deg_kernel(const int* __restrict__ dst) {
    int e = blockIdx.x * blockDim.x + threadIdx.x;
    if (e < EE) atomicAdd(&g_deg[dst[e]], 1);
}

__global__ void scan_blocks_kernel() {
    __shared__ int sh[1024];
    int t = threadIdx.x;
    int i = blockIdx.x * 1024 + t;
    int v = (i < NN) ? g_deg[i] : 0;
    if (i < NN) g_dinv[i] = rsqrtf((float)v + 1.0f);   // fused dinv
    sh[t] = v;
    __syncthreads();
    #pragma unroll
    for (int off = 1; off < 1024; off <<= 1) {
        int add = (t >= off) ? sh[t - off] : 0;
        __syncthreads();
        sh[t] += add;
        __syncthreads();
    }
    if (i < NN) g_rowptr[i] = sh[t] - v;   // exclusive prefix
    if (t == 1023) g_partials[blockIdx.x] = sh[1023];
}

__global__ void scan_partials_kernel() {
    if (threadIdx.x == 0 && blockIdx.x == 0) {
        int acc = 0;
        for (int b = 0; b < NB; b++) {
            int t = g_partials[b];
            g_partials[b] = acc;
            acc += t;
        }
    }
}

__global__ void add_offsets_kernel() {
    int i = blockIdx.x * blockDim.x + threadIdx.x;
    if (i < NN) {
        int v = g_rowptr[i] + g_partials[i >> 10];
        g_rowptr[i] = v;
        g_cursor[i] = v;
    }
}

__global__ void fill_csr_kernel(const int* __restrict__ src, const int* __restrict__ dst) {
    int e = blockIdx.x * blockDim.x + threadIdx.x;
    if (e < EE) {
        int s = src[e];
        int pos = atomicAdd(&g_cursor[dst[e]], 1);
        g_csrc[pos] = s;
        g_cw[pos] = g_dinv[s];
    }
}

// ---------------- weight split: out[n] = [hi(K) | lo(K)] -------------------
__global__ void conv_w_kernel(const float* __restrict__ in,
                              __nv_bfloat16* __restrict__ out,
                              int Nr, int Npad, int K) {
    int idx = blockIdx.x * blockDim.x + threadIdx.x;
    if (idx >= Npad * K) return;
    int n = idx / K;
    int k = idx - n * K;
    __nv_bfloat16 hi = __float2bfloat16(0.0f), loh = __float2bfloat16(0.0f);
    if (n < Nr) {
        float x = in[(size_t)n * K + k];
        hi = __float2bfloat16(x);
        float lo = x - __bfloat162float(hi);
        loh = __float2bfloat16(lo);
    }
    size_t base = (size_t)n * (2 * K);
    out[base + k]     = hi;
    out[base + K + k] = loh;
}

// ---------------- fused weight: Wf = Wout @ W2; biasf = bout + Wout@b2 ------
__global__ void fuse_w_kernel(const float* __restrict__ Wout, const float* __restrict__ W2,
                              const float* __restrict__ b2, const float* __restrict__ bout) {
    __shared__ float sh[256];
    int c = blockIdx.x;          // 0..39
    int i = threadIdx.x;         // 0..255
    float acc = 0.0f;
    #pragma unroll 4
    for (int o = 0; o < HH; o++)
        acc += Wout[c * HH + o] * W2[(size_t)o * HH + i];
    g_wf32[c * HH + i] = acc;
    sh[i] = Wout[c * HH + i] * b2[i];
    __syncthreads();
    for (int off = 128; off > 0; off >>= 1) {
        if (i < off) sh[i] += sh[i + off];
        __syncthreads();
    }
    if (i == 0) g_biasf[c] = bout[c] + sh[0];
}

// ---------------- agg(x) with split-bf16 output -----------------------------
__global__ __launch_bounds__(FF)
void aggregate_split_kernel(const float* __restrict__ h) {
    int i = blockIdx.x;
    int c = threadIdx.x;
    __shared__ int   s_src[FF];
    __shared__ float s_w[FF];

    int start = g_rowptr[i];
    int d = g_deg[i];
    float di = g_dinv[i];
    float acc = 0.0f;

    if (d <= FF) {
        if (c < d) {
            s_src[c] = g_csrc[start + c];
            s_w[c] = g_cw[start + c];
        }
        __syncthreads();
        #pragma unroll 4
        for (int j = 0; j < d; j++)
            acc += s_w[j] * h[(size_t)s_src[j] * FF + c];
    } else {
        for (int base = 0; base < d; base += FF) {
            int n = d - base;
            if (n > FF) n = FF;
            __syncthreads();
            if (c < n) {
                s_src[c] = g_csrc[start + base + c];
                s_w[c] = g_cw[start + base + c];
            }
            __syncthreads();
            #pragma unroll 4
            for (int j = 0; j < n; j++)
                acc += s_w[j] * h[(size_t)s_src[j] * FF + c];
        }
    }

    float v = di * acc + di * di * h[(size_t)i * FF + c];
    __nv_bfloat16 hi = __float2bfloat16(v);
    __nv_bfloat16 lo = __float2bfloat16(v - __bfloat162float(hi));
    size_t b = (size_t)i * (2 * FF);
    g_a16[b + c]      = hi;
    g_a16[b + FF + c] = lo;
}

// ---------------- mma helpers -----------------------------------------------
__device__ __forceinline__ void ldmx4(uint32_t* r, const __nv_bfloat16* p) {
    uint32_t addr = (uint32_t)__cvta_generic_to_shared(p);
    asm volatile("ldmatrix.sync.aligned.m8n8.x4.shared.b16 {%0,%1,%2,%3}, [%4];"
                 : "=r"(r[0]), "=r"(r[1]), "=r"(r[2]), "=r"(r[3]) : "r"(addr));
}

__device__ __forceinline__ void mma16816(float* d, const uint32_t* a, const uint32_t* b) {
    asm volatile(
        "mma.sync.aligned.m16n8k16.row.col.f32.bf16.bf16.f32 "
        "{%0,%1,%2,%3}, {%4,%5,%6,%7}, {%8,%9}, {%0,%1,%2,%3};"
        : "+f"(d[0]), "+f"(d[1]), "+f"(d[2]), "+f"(d[3])
        : "r"(a[0]), "r"(a[1]), "r"(a[2]), "r"(a[3]), "r"(b[0]), "r"(b[1]));
}

// ---------------- B2B kernel: p = relu(a16*W1'^T+b1) * Wf'^T ----------------
// Block = 128 nodes. 4 n-tiles of 64 h-columns:
//   phase A: h_tile[128,64] via 3-term bf16 split GEMM (K=128, logical 384)
//   split h_tile -> SMEM Hs [hi64|lo64] stride 136
//   phase B: p[128,64acc] += Hs' (logical K=192) x Wfs'
// Warp grid both phases: 4 row-warps x 2 col-warps, MI=2, NI=4.
#define HSTR 136
#define ATP 40

__global__ __launch_bounds__(256, 2)
void b2b_kernel(const __nv_bfloat16* __restrict__ A,
                const __nv_bfloat16* __restrict__ W1s,
                const __nv_bfloat16* __restrict__ Wf16,
                const float* __restrict__ b1,
                float* __restrict__ P, int M) {
    extern __shared__ __nv_bfloat16 smem[];
    __nv_bfloat16* As  = smem;                 // 128*40  = 5120
    __nv_bfloat16* Bs  = smem + 5120;          // 64*40   = 2560
    __nv_bfloat16* Hs  = smem + 7680;          // 128*136 = 17408
    __nv_bfloat16* Wfs = smem + 25088;         // 64*136  = 8704

    int tid = threadIdx.x;
    int bm = blockIdx.x * 128;
    int wid = tid >> 5;
    int lane = tid & 31;
    int wm = wid >> 1;          // 0..3 : 32-row slab
    int wn = wid & 1;           // 0..1 : 32-col slab

    float acc2[2][4][4];
    #pragma unroll
    for (int i = 0; i < 2; i++)
        #pragma unroll
        for (int j = 0; j < 4; j++)
            #pragma unroll
            for (int v = 0; v < 4; v++) acc2[i][j][v] = 0.0f;

    for (int nt = 0; nt < 4; nt++) {
        // ---------------- phase A: h_tile = a' * W1'(rows nt*64..+64)^T ----
        float acc[2][4][4];
        #pragma unroll
        for (int i = 0; i < 2; i++)
            #pragma unroll
            for (int j = 0; j < 4; j++)
                #pragma unroll
                for (int v = 0; v < 4; v++) acc[i][j][v] = 0.0f;

        for (int k0 = 0; k0 < 3 * FF; k0 += 32) {
            int seg = k0 >> 7;              // k0/128
            int kk = k0 & 127;
            int aoff = (seg == 2 ? FF : 0) + kk;
            int boff = (seg == 1 ? FF : 0) + kk;

            // stage A: 128 rows x 32 halves = 512 uint4 over 256 threads
            #pragma unroll
            for (int it = 0; it < 2; it++) {
                int idx = tid + it * 256;
                int r = idx >> 2;
                int q = idx & 3;
                int m = bm + r;
                uint4 v = make_uint4(0u, 0u, 0u, 0u);
                if (m < M) v = *(const uint4*)&A[(size_t)m * (2 * FF) + aoff + q * 8];
                *(uint4*)&As[r * ATP + q * 8] = v;
            }
            // stage B: 64 rows x 32 halves = 256 uint4 over 256 threads
            {
                int r = tid >> 2;
                int q = tid & 3;
                uint4 v = *(const uint4*)&W1s[(size_t)(nt * 64 + r) * (2 * FF) + boff + q * 8];
                *(uint4*)&Bs[r * ATP + q * 8] = v;
            }
            __syncthreads();

            #pragma unroll
            for (int ks = 0; ks < 2; ks++) {
                uint32_t afr[2][4];
                #pragma unroll
                for (int mi = 0; mi < 2; mi++) {
                    int row = wm * 32 + mi * 16 + (lane & 15);
                    int col = ks * 16 + (lane >> 4) * 8;
                    ldmx4(afr[mi], &As[row * ATP + col]);
                }
                uint32_t bfr[2][4];
                #pragma unroll
                for (int pr = 0; pr < 2; pr++) {
                    int row = wn * 32 + pr * 16 + (lane & 15);
                    int col = ks * 16 + (lane >> 4) * 8;
                    ldmx4(bfr[pr], &Bs[row * ATP + col]);
                }
                #pragma unroll
                for (int mi = 0; mi < 2; mi++)
                    #pragma unroll
                    for (int ni = 0; ni < 4; ni++) {
                        uint32_t bb[2];
                        bb[0] = bfr[ni >> 1][ni & 1];
                        bb[1] = bfr[ni >> 1][(ni & 1) + 2];
                        mma16816(acc[mi][ni], afr[mi], bb);
                    }
            }
            __syncthreads();
        }

        // epilogue A: bias + relu + split -> Hs [hi(64)|lo(64)] stride HSTR
        #pragma unroll
        for (int mi = 0; mi < 2; mi++)
            #pragma unroll
            for (int ni = 0; ni < 4; ni++) {
                int row0 = wm * 32 + mi * 16 + (lane >> 2);
                int col0 = wn * 32 + ni * 8 + 2 * (lane & 3);
                int gc = nt * 64 + col0;
                float bv0 = b1[gc];
                float bv1 = b1[gc + 1];
                #pragma unroll
                for (int half = 0; half < 2; half++) {
                    int row = row0 + half * 8;
                    float a0 = acc[mi][ni][half * 2 + 0] + bv0;
                    float a1 = acc[mi][ni][half * 2 + 1] + bv1;
                    a0 = fmaxf(a0, 0.0f);
                    a1 = fmaxf(a1, 0.0f);
                    __nv_bfloat16 h0 = __float2bfloat16(a0);
                    __nv_bfloat16 h1 = __float2bfloat16(a1);
                    __nv_bfloat162 hip; hip.x = h0; hip.y = h1;
                    __nv_bfloat162 lop;
                    lop.x = __float2bfloat16(a0 - __bfloat162float(h0));
                    lop.y = __float2bfloat16(a1 - __bfloat162float(h1));
                    *(__nv_bfloat162*)&Hs[row * HSTR + col0]      = hip;
                    *(__nv_bfloat162*)&Hs[row * HSTR + 64 + col0] = lop;
                }
            }

        // stage Wf chunk: 64 rows x [hi64|lo64] -> Wfs stride HSTR
        // 64*16 = 1024 uint4 over 256 threads = 4 iterations
        for (int idx = tid; idx < 64 * 16; idx += 256) {
            int r = idx >> 4;               // row 0..63
            int sub = idx & 15;             // 16 uint4 per row (128 halves)
            int part = sub >> 3;            // 0=hi, 1=lo
            int q = sub & 7;                // 8 uint4 per 64-half part
            uint4 v = *(const uint4*)&Wf16[(size_t)r * (2 * HH) + part * HH + nt * 64 + q * 8];
            *(uint4*)&Wfs[r * HSTR + part * 64 + q * 8] = v;
        }
        __syncthreads();

        // ---------------- phase B: p += Hs' (K=64, logical 192) x Wfs'^T ---
        for (int k0 = 0; k0 < 3 * 64; k0 += 16) {
            int seg = k0 >> 6;
            int kk = k0 & 63;
            int aoff = (seg == 2 ? 64 : 0) + kk;
            int boff = (seg == 1 ? 64 : 0) + kk;

            uint32_t afr[2][4];
            #pragma unroll
            for (int mi = 0; mi < 2; mi++) {
                int row = wm * 32 + mi * 16 + (lane & 15);
                ldmx4(afr[mi], &Hs[row * HSTR + aoff + (lane >> 4) * 8]);
            }
            uint32_t bfr[2][4];
            #pragma unroll
            for (int pr = 0; pr < 2; pr++) {
                int row = wn * 32 + pr * 16 + (lane & 15);
                ldmx4(bfr[pr], &Wfs[row * HSTR + boff + (lane >> 4) * 8]);
            }
            #pragma unroll
            for (int mi = 0; mi < 2; mi++)
                #pragma unroll
                for (int ni = 0; ni < 4; ni++) {
                    uint32_t bb[2];
                    bb[0] = bfr[ni >> 1][ni & 1];
                    bb[1] = bfr[ni >> 1][(ni & 1) + 2];
                    mma16816(acc2[mi][ni], afr[mi], bb);
                }
        }
        __syncthreads();   // protect Hs/Wfs before next nt overwrites
    }

    // epilogue: write p (stride PSTR, cols < CC, rows < M)
    #pragma unroll
    for (int mi = 0; mi < 2; mi++)
        #pragma unroll
        for (int ni = 0; ni < 4; ni++) {
            int col0 = wn * 32 + ni * 8 + 2 * (lane & 3);
            if (col0 >= CC) continue;
            int row0 = bm + wm * 32 + mi * 16 + (lane >> 2);
            if (row0 < M)
                *(float2*)&P[(size_t)row0 * PSTR + col0] =
                    make_float2(acc2[mi][ni][0], acc2[mi][ni][1]);
            if (row0 + 8 < M)
                *(float2*)&P[(size_t)(row0 + 8) * PSTR + col0] =
                    make_float2(acc2[mi][ni][2], acc2[mi][ni][3]);
        }
}

// ---------------- final aggregation at C=40: warp per node ------------------
__global__ __launch_bounds__(256)
void aggregate_final_kernel(float* __restrict__ out) {
    int node = blockIdx.x * 8 + (threadIdx.x >> 5);
    int lane = threadIdx.x & 31;
    if (node >= NN) return;

    const float* __restrict__ p = g_p;
    int start = g_rowptr[node];
    int d = g_deg[node];
    float di = g_dinv[node];

    float acc0 = 0.0f, acc1 = 0.0f;
    #pragma unroll 4
    for (int j = 0; j < d; j++) {
        int s = g_csrc[start + j];        // uniform across warp -> broadcast
        float w = g_cw[start + j];
        const float* row = &p[(size_t)s * PSTR];
        acc0 += w * row[lane];
        if (lane < CC - 32) acc1 += w * row[32 + lane];
    }

    const float* self = &p[(size_t)node * PSTR];
    float v0 = di * acc0 + di * di * self[lane] + g_biasf[lane];
    out[(size_t)node * CC + lane] = v0;
    if (lane < CC - 32) {
        float v1 = di * acc1 + di * di * self[32 + lane] + g_biasf[32 + lane];
        out[(size_t)node * CC + 32 + lane] = v1;
    }
}

// ---------------- launch ----------------------------------------------------
extern "C" void kernel_launch(void* const* d_in, const int* in_sizes, int n_in,
                              void* d_out, int out_size) {
    const float* x    = (const float*)d_in[0];
    const int*   ei   = (const int*)d_in[1];
    const float* W1   = (const float*)d_in[2];
    const float* b1   = (const float*)d_in[3];
    const float* W2   = (const float*)d_in[4];
    const float* b2   = (const float*)d_in[5];
    const float* Wout = (const float*)d_in[6];
    const float* bout = (const float*)d_in[7];
    float* out = (float*)d_out;

    const int* src = ei;         // edge_index[0]
    const int* dst = ei + EE;    // edge_index[1]

    __nv_bfloat16* a16;  cudaGetSymbolAddress((void**)&a16, g_a16);
    __nv_bfloat16* w16;  cudaGetSymbolAddress((void**)&w16, g_w16);
    __nv_bfloat16* wf16; cudaGetSymbolAddress((void**)&wf16, g_wf16);
    float* pbuf; cudaGetSymbolAddress((void**)&pbuf, g_p);
    float* wf32; cudaGetSymbolAddress((void**)&wf32, g_wf32);

    cudaFuncSetAttribute(b2b_kernel, cudaFuncAttributeMaxDynamicSharedMemorySize,
                         33792 * (int)sizeof(__nv_bfloat16));

    // ---- CSR build ----
    zero_deg_kernel<<<(NN + 255) / 256, 256>>>();
    count_deg_kernel<<<(EE + 255) / 256, 256>>>(dst);
    scan_blocks_kernel<<<NB, 1024>>>();          // also computes dinv
    scan_partials_kernel<<<1, 32>>>();
    add_offsets_kernel<<<(NN + 255) / 256, 256>>>();
    fill_csr_kernel<<<(EE + 255) / 256, 256>>>(src, dst);

    // ---- weight prep ----
    conv_w_kernel<<<(HH * FF + 255) / 256, 256>>>(W1, w16, HH, HH, FF);
    fuse_w_kernel<<<CC, 256>>>(Wout, W2, b2, bout);
    conv_w_kernel<<<(64 * HH + 255) / 256, 256>>>(wf32, wf16, CC, 64, HH);

    // ---- agg(x) -> split a16 ----
    aggregate_split_kernel<<<NN, FF>>>(x);

    // ---- fused B2B: p = relu(a16 @ W1'^T + b1) @ Wf'^T ----
    b2b_kernel<<<(NN + 127) / 128, 256, 33792 * sizeof(__nv_bfloat16)>>>(
        a16, w16, wf16, b1, pbuf, NN);

    // ---- final aggregation at C=40 -> out ----
    aggregate_final_kernel<<<(NN + 7) / 8, 256>>>(out);
}

// round 9
// speedup vs baseline: 4.3806x; 1.0474x over previous
#include <cuda_runtime.h>
#include <cuda_bf16.h>
#include <cstdint>

#define NN 50000
#define EE 800000
#define FF 128
#define HH 256
#define CC 40
#define PSTR 64                   // padded p row stride
#define NB ((NN + 1023) / 1024)   // 49 scan blocks

// ---------------- scratch (device globals; no runtime allocation) ----------
__device__ __nv_bfloat16 g_a16[(size_t)NN * 2 * FF];   // split agg(x)  [N,256]=[hi|lo]
__device__ __nv_bfloat16 g_w16[(size_t)HH * 2 * FF];   // split W1 [256][hi128|lo128]
__device__ __nv_bfloat16 g_wf16[(size_t)64 * 2 * HH];  // split Wf [64][hi256|lo256]
__device__ float g_p[(size_t)NN * PSTR];               // pre-agg logits [N,40] pad 64
__device__ float g_biasf[CC];                          // fused bias
__device__ int   g_deg[NN];
__device__ float g_dinv[NN];
__device__ int   g_rowptr[NN];
__device__ int   g_cursor[NN];
__device__ int   g_partials[64];
__device__ int   g_csrc[EE];
__device__ float g_cw[EE];                             // per-edge dinv[src]

// ---------------- CSR build ------------------------------------------------
__global__ void zero_deg_kernel() {
    int i = blockIdx.x * blockDim.x + threadIdx.x;
    if (i < NN) g_deg[i] = 0;
}

__global__ void count_deg_kernel(const int* __restrict__ dst) {
    int e = blockIdx.x * blockDim.x + threadIdx.x;
    if (e < EE) atomicAdd(&g_deg[dst[e]], 1);
}

__global__ void scan_blocks_kernel() {
    __shared__ int sh[1024];
    int t = threadIdx.x;
    int i = blockIdx.x * 1024 + t;
    int v = (i < NN) ? g_deg[i] : 0;
    if (i < NN) g_dinv[i] = rsqrtf((float)v + 1.0f);   // fused dinv
    sh[t] = v;
    __syncthreads();
    #pragma unroll
    for (int off = 1; off < 1024; off <<= 1) {
        int add = (t >= off) ? sh[t - off] : 0;
        __syncthreads();
        sh[t] += add;
        __syncthreads();
    }
    if (i < NN) g_rowptr[i] = sh[t] - v;   // exclusive prefix within block
    if (t == 1023) g_partials[blockIdx.x] = sh[1023];   // raw block sums
}

// add block-prefix of partials inline (warp-reduce over <=49 raw sums)
__global__ void add_offsets_kernel() {
    __shared__ int s_pref;
    int i = blockIdx.x * blockDim.x + threadIdx.x;
    int grp = (blockIdx.x * 256) >> 10;   // constant per 256-thread block
    if (threadIdx.x < 32) {
        int acc = 0;
        for (int b = threadIdx.x; b < grp; b += 32) acc += g_partials[b];
        #pragma unroll
        for (int off = 16; off; off >>= 1) acc += __shfl_xor_sync(~0u, acc, off);
        if (threadIdx.x == 0) s_pref = acc;
    }
    __syncthreads();
    if (i < NN) {
        int v = g_rowptr[i] + s_pref;
        g_rowptr[i] = v;
        g_cursor[i] = v;
    }
}

__global__ void fill_csr_kernel(const int* __restrict__ src, const int* __restrict__ dst) {
    int e = blockIdx.x * blockDim.x + threadIdx.x;
    if (e < EE) {
        int s = src[e];
        int pos = atomicAdd(&g_cursor[dst[e]], 1);
        g_csrc[pos] = s;
        g_cw[pos] = g_dinv[s];
    }
}

// ---------------- combined weight prep --------------------------------------
// blocks 0..127   : split W1 (256x128) -> g_w16 rows [hi128|lo128]
// blocks 128..167 : c = b-128: Wf row c = Wout[c]@W2 (fp32), split -> g_wf16
//                   [hi256|lo256]; also biasf[c] = bout[c] + Wout[c]@b2
// block 168       : zero-pad g_wf16 rows 40..63
__global__ void prep_kernel(const float* __restrict__ W1, const float* __restrict__ W2,
                            const float* __restrict__ Wout, const float* __restrict__ b2,
                            const float* __restrict__ bout) {
    __shared__ float sh[256];
    int b = blockIdx.x;
    int t = threadIdx.x;
    if (b < 128) {
        int idx = b * 256 + t;
        int n = idx >> 7;            // row 0..255
        int k = idx & 127;
        float x = W1[(size_t)n * FF + k];
        __nv_bfloat16 hi = __float2bfloat16(x);
        __nv_bfloat16 lo = __float2bfloat16(x - __bfloat162float(hi));
        g_w16[(size_t)n * (2 * FF) + k]      = hi;
        g_w16[(size_t)n * (2 * FF) + FF + k] = lo;
    } else if (b < 168) {
        int c = b - 128;             // 0..39
        float wc = Wout[(size_t)c * HH + t];
        float acc = 0.0f;
        #pragma unroll 4
        for (int o = 0; o < HH; o++)
            acc += Wout[(size_t)c * HH + o] * W2[(size_t)o * HH + t];
        __nv_bfloat16 hi = __float2bfloat16(acc);
        __nv_bfloat16 lo = __float2bfloat16(acc - __bfloat162float(hi));
        g_wf16[(size_t)c * (2 * HH) + t]      = hi;
        g_wf16[(size_t)c * (2 * HH) + HH + t] = lo;
        sh[t] = wc * b2[t];
        __syncthreads();
        for (int off = 128; off > 0; off >>= 1) {
            if (t < off) sh[t] += sh[t + off];
            __syncthreads();
        }
        if (t == 0) g_biasf[c] = bout[c] + sh[0];
    } else {
        __nv_bfloat16 z = __float2bfloat16(0.0f);
        for (int idx = t; idx < 24 * 2 * HH; idx += 256)
            g_wf16[(size_t)40 * (2 * HH) + idx] = z;
    }
}

// ---------------- agg(x) with split-bf16 output -----------------------------
__global__ __launch_bounds__(FF)
void aggregate_split_kernel(const float* __restrict__ h) {
    int i = blockIdx.x;
    int c = threadIdx.x;
    __shared__ int   s_src[FF];
    __shared__ float s_w[FF];

    int start = g_rowptr[i];
    int d = g_deg[i];
    float di = g_dinv[i];
    float acc = 0.0f;

    if (d <= FF) {
        if (c < d) {
            s_src[c] = g_csrc[start + c];
            s_w[c] = g_cw[start + c];
        }
        __syncthreads();
        #pragma unroll 4
        for (int j = 0; j < d; j++)
            acc += s_w[j] * h[(size_t)s_src[j] * FF + c];
    } else {
        for (int base = 0; base < d; base += FF) {
            int n = d - base;
            if (n > FF) n = FF;
            __syncthreads();
            if (c < n) {
                s_src[c] = g_csrc[start + base + c];
                s_w[c] = g_cw[start + base + c];
            }
            __syncthreads();
            #pragma unroll 4
            for (int j = 0; j < n; j++)
                acc += s_w[j] * h[(size_t)s_src[j] * FF + c];
        }
    }

    float v = di * acc + di * di * h[(size_t)i * FF + c];
    __nv_bfloat16 hi = __float2bfloat16(v);
    __nv_bfloat16 lo = __float2bfloat16(v - __bfloat162float(hi));
    size_t b = (size_t)i * (2 * FF);
    g_a16[b + c]      = hi;
    g_a16[b + FF + c] = lo;
}

// ---------------- mma helpers -----------------------------------------------
__device__ __forceinline__ void ldmx4(uint32_t* r, const __nv_bfloat16* p) {
    uint32_t addr = (uint32_t)__cvta_generic_to_shared(p);
    asm volatile("ldmatrix.sync.aligned.m8n8.x4.shared.b16 {%0,%1,%2,%3}, [%4];"
                 : "=r"(r[0]), "=r"(r[1]), "=r"(r[2]), "=r"(r[3]) : "r"(addr));
}

__device__ __forceinline__ void mma16816(float* d, const uint32_t* a, const uint32_t* b) {
    asm volatile(
        "mma.sync.aligned.m16n8k16.row.col.f32.bf16.bf16.f32 "
        "{%0,%1,%2,%3}, {%4,%5,%6,%7}, {%8,%9}, {%0,%1,%2,%3};"
        : "+f"(d[0]), "+f"(d[1]), "+f"(d[2]), "+f"(d[3])
        : "r"(a[0]), "r"(a[1]), "r"(a[2]), "r"(a[3]), "r"(b[0]), "r"(b[1]));
}

// ---------------- B2B kernel: p = relu(a16*W1'^T+b1) * Wf'^T ----------------
// Block = 128 nodes. 4 n-tiles of 64 h-columns.
// Phase A restructured: per 32-col stored chunk, stage Ahi,Alo,Whi,Wlo once
// and issue the 3 logical products (hi*hi, hi*lo, lo*hi).
#define HSTR 136
#define ATP 40

__global__ __launch_bounds__(256, 2)
void b2b_kernel(const __nv_bfloat16* __restrict__ A,
                const __nv_bfloat16* __restrict__ W1s,
                const __nv_bfloat16* __restrict__ Wf16,
                const float* __restrict__ b1,
                float* __restrict__ P, int M) {
    extern __shared__ __nv_bfloat16 smem[];
    __nv_bfloat16* Ahi = smem;                 // 128*40 = 5120
    __nv_bfloat16* Alo = smem + 5120;          // 5120
    __nv_bfloat16* Bhi = smem + 10240;         // 64*40 = 2560
    __nv_bfloat16* Blo = smem + 12800;         // 2560
    __nv_bfloat16* Hs  = smem + 15360;         // 128*136 = 17408
    __nv_bfloat16* Wfs = smem + 32768;         // 64*136 = 8704  (total 41472)

    int tid = threadIdx.x;
    int bm = blockIdx.x * 128;
    int wid = tid >> 5;
    int lane = tid & 31;
    int wm = wid >> 1;          // 0..3 : 32-row slab
    int wn = wid & 1;           // 0..1 : 32-col slab

    float acc2[2][4][4];
    #pragma unroll
    for (int i = 0; i < 2; i++)
        #pragma unroll
        for (int j = 0; j < 4; j++)
            #pragma unroll
            for (int v = 0; v < 4; v++) acc2[i][j][v] = 0.0f;

    for (int nt = 0; nt < 4; nt++) {
        // ---------------- phase A ----------------
        float acc[2][4][4];
        #pragma unroll
        for (int i = 0; i < 2; i++)
            #pragma unroll
            for (int j = 0; j < 4; j++)
                #pragma unroll
                for (int v = 0; v < 4; v++) acc[i][j][v] = 0.0f;

        for (int kk = 0; kk < FF; kk += 32) {
            // stage A hi+lo: 128 rows x 32 halves each
            #pragma unroll
            for (int it = 0; it < 2; it++) {
                int idx = tid + it * 256;
                int r = idx >> 2;
                int q = idx & 3;
                int m = bm + r;
                uint4 vh = make_uint4(0u, 0u, 0u, 0u);
                uint4 vl = make_uint4(0u, 0u, 0u, 0u);
                if (m < M) {
                    const __nv_bfloat16* base = &A[(size_t)m * (2 * FF) + kk + q * 8];
                    vh = *(const uint4*)base;
                    vl = *(const uint4*)(base + FF);
                }
                *(uint4*)&Ahi[r * ATP + q * 8] = vh;
                *(uint4*)&Alo[r * ATP + q * 8] = vl;
            }
            // stage W1 hi+lo: 64 rows x 32 halves each
            {
                int r = tid >> 2;
                int q = tid & 3;
                const __nv_bfloat16* base =
                    &W1s[(size_t)(nt * 64 + r) * (2 * FF) + kk + q * 8];
                *(uint4*)&Bhi[r * ATP + q * 8] = *(const uint4*)base;
                *(uint4*)&Blo[r * ATP + q * 8] = *(const uint4*)(base + FF);
            }
            __syncthreads();

            #pragma unroll
            for (int ks = 0; ks < 2; ks++) {
                int acol = ks * 16 + (lane >> 4) * 8;
                uint32_t ah[2][4], al[2][4];
                #pragma unroll
                for (int mi = 0; mi < 2; mi++) {
                    int row = wm * 32 + mi * 16 + (lane & 15);
                    ldmx4(ah[mi], &Ahi[row * ATP + acol]);
                    ldmx4(al[mi], &Alo[row * ATP + acol]);
                }
                uint32_t bh[2][4], bl[2][4];
                #pragma unroll
                for (int pr = 0; pr < 2; pr++) {
                    int row = wn * 32 + pr * 16 + (lane & 15);
                    ldmx4(bh[pr], &Bhi[row * ATP + acol]);
                    ldmx4(bl[pr], &Blo[row * ATP + acol]);
                }
                #pragma unroll
                for (int mi = 0; mi < 2; mi++)
                    #pragma unroll
                    for (int ni = 0; ni < 4; ni++) {
                        uint32_t bb[2];
                        // hi * hi
                        bb[0] = bh[ni >> 1][ni & 1];
                        bb[1] = bh[ni >> 1][(ni & 1) + 2];
                        mma16816(acc[mi][ni], ah[mi], bb);
                        // lo * hi
                        mma16816(acc[mi][ni], al[mi], bb);
                        // hi * lo
                        bb[0] = bl[ni >> 1][ni & 1];
                        bb[1] = bl[ni >> 1][(ni & 1) + 2];
                        mma16816(acc[mi][ni], ah[mi], bb);
                    }
            }
            __syncthreads();
        }

        // epilogue A: bias + relu + split -> Hs [hi(64)|lo(64)] stride HSTR
        #pragma unroll
        for (int mi = 0; mi < 2; mi++)
            #pragma unroll
            for (int ni = 0; ni < 4; ni++) {
                int row0 = wm * 32 + mi * 16 + (lane >> 2);
                int col0 = wn * 32 + ni * 8 + 2 * (lane & 3);
                int gc = nt * 64 + col0;
                float bv0 = b1[gc];
                float bv1 = b1[gc + 1];
                #pragma unroll
                for (int half = 0; half < 2; half++) {
                    int row = row0 + half * 8;
                    float a0 = acc[mi][ni][half * 2 + 0] + bv0;
                    float a1 = acc[mi][ni][half * 2 + 1] + bv1;
                    a0 = fmaxf(a0, 0.0f);
                    a1 = fmaxf(a1, 0.0f);
                    __nv_bfloat16 h0 = __float2bfloat16(a0);
                    __nv_bfloat16 h1 = __float2bfloat16(a1);
                    __nv_bfloat162 hip; hip.x = h0; hip.y = h1;
                    __nv_bfloat162 lop;
                    lop.x = __float2bfloat16(a0 - __bfloat162float(h0));
                    lop.y = __float2bfloat16(a1 - __bfloat162float(h1));
                    *(__nv_bfloat162*)&Hs[row * HSTR + col0]      = hip;
                    *(__nv_bfloat162*)&Hs[row * HSTR + 64 + col0] = lop;
                }
            }

        // stage Wf chunk: 64 rows x [hi64|lo64] -> Wfs stride HSTR
        for (int idx = tid; idx < 64 * 16; idx += 256) {
            int r = idx >> 4;
            int sub = idx & 15;
            int part = sub >> 3;            // 0=hi, 1=lo
            int q = sub & 7;
            uint4 v = *(const uint4*)&Wf16[(size_t)r * (2 * HH) + part * HH + nt * 64 + q * 8];
            *(uint4*)&Wfs[r * HSTR + part * 64 + q * 8] = v;
        }
        __syncthreads();

        // ---------------- phase B: p += Hs' (K=64, logical 192) x Wfs'^T ---
        for (int k0 = 0; k0 < 3 * 64; k0 += 16) {
            int seg = k0 >> 6;
            int kk = k0 & 63;
            int aoff = (seg == 2 ? 64 : 0) + kk;
            int boff = (seg == 1 ? 64 : 0) + kk;

            uint32_t afr[2][4];
            #pragma unroll
            for (int mi = 0; mi < 2; mi++) {
                int row = wm * 32 + mi * 16 + (lane & 15);
                ldmx4(afr[mi], &Hs[row * HSTR + aoff + (lane >> 4) * 8]);
            }
            uint32_t bfr[2][4];
            #pragma unroll
            for (int pr = 0; pr < 2; pr++) {
                int row = wn * 32 + pr * 16 + (lane & 15);
                ldmx4(bfr[pr], &Wfs[row * HSTR + boff + (lane >> 4) * 8]);
            }
            #pragma unroll
            for (int mi = 0; mi < 2; mi++)
                #pragma unroll
                for (int ni = 0; ni < 4; ni++) {
                    uint32_t bb[2];
                    bb[0] = bfr[ni >> 1][ni & 1];
                    bb[1] = bfr[ni >> 1][(ni & 1) + 2];
                    mma16816(acc2[mi][ni], afr[mi], bb);
                }
        }
        __syncthreads();   // protect Hs/Wfs before next nt overwrites
    }

    // epilogue: write p (stride PSTR, cols < CC, rows < M)
    #pragma unroll
    for (int mi = 0; mi < 2; mi++)
        #pragma unroll
        for (int ni = 0; ni < 4; ni++) {
            int col0 = wn * 32 + ni * 8 + 2 * (lane & 3);
            if (col0 >= CC) continue;
            int row0 = bm + wm * 32 + mi * 16 + (lane >> 2);
            if (row0 < M)
                *(float2*)&P[(size_t)row0 * PSTR + col0] =
                    make_float2(acc2[mi][ni][0], acc2[mi][ni][1]);
            if (row0 + 8 < M)
                *(float2*)&P[(size_t)(row0 + 8) * PSTR + col0] =
                    make_float2(acc2[mi][ni][2], acc2[mi][ni][3]);
        }
}

// ---------------- final aggregation at C=40: warp per node ------------------
__global__ __launch_bounds__(256)
void aggregate_final_kernel(float* __restrict__ out) {
    int node = blockIdx.x * 8 + (threadIdx.x >> 5);
    int lane = threadIdx.x & 31;
    if (node >= NN) return;

    const float* __restrict__ p = g_p;
    int start = g_rowptr[node];
    int d = g_deg[node];
    float di = g_dinv[node];

    float acc0 = 0.0f, acc1 = 0.0f;
    #pragma unroll 4
    for (int j = 0; j < d; j++) {
        int s = g_csrc[start + j];        // uniform across warp -> broadcast
        float w = g_cw[start + j];
        const float* row = &p[(size_t)s * PSTR];
        acc0 += w * row[lane];
        if (lane < CC - 32) acc1 += w * row[32 + lane];
    }

    const float* self = &p[(size_t)node * PSTR];
    float v0 = di * acc0 + di * di * self[lane] + g_biasf[lane];
    out[(size_t)node * CC + lane] = v0;
    if (lane < CC - 32) {
        float v1 = di * acc1 + di * di * self[32 + lane] + g_biasf[32 + lane];
        out[(size_t)node * CC + 32 + lane] = v1;
    }
}

// ---------------- launch ----------------------------------------------------
extern "C" void kernel_launch(void* const* d_in, const int* in_sizes, int n_in,
                              void* d_out, int out_size) {
    const float* x    = (const float*)d_in[0];
    const int*   ei   = (const int*)d_in[1];
    const float* W1   = (const float*)d_in[2];
    const float* b1   = (const float*)d_in[3];
    const float* W2   = (const float*)d_in[4];
    const float* b2   = (const float*)d_in[5];
    const float* Wout = (const float*)d_in[6];
    const float* bout = (const float*)d_in[7];
    float* out = (float*)d_out;

    const int* src = ei;         // edge_index[0]
    const int* dst = ei + EE;    // edge_index[1]

    __nv_bfloat16* a16;  cudaGetSymbolAddress((void**)&a16, g_a16);
    __nv_bfloat16* w16;  cudaGetSymbolAddress((void**)&w16, g_w16);
    __nv_bfloat16* wf16; cudaGetSymbolAddress((void**)&wf16, g_wf16);
    float* pbuf; cudaGetSymbolAddress((void**)&pbuf, g_p);

    cudaFuncSetAttribute(b2b_kernel, cudaFuncAttributeMaxDynamicSharedMemorySize,
                         41472 * (int)sizeof(__nv_bfloat16));

    // ---- weight prep (one kernel) ----
    prep_kernel<<<169, 256>>>(W1, W2, Wout, b2, bout);

    // ---- CSR build ----
    zero_deg_kernel<<<(NN + 255) / 256, 256>>>();
    count_deg_kernel<<<(EE + 255) / 256, 256>>>(dst);
    scan_blocks_kernel<<<NB, 1024>>>();          // also computes dinv
    add_offsets_kernel<<<(NN + 255) / 256, 256>>>();   // inline partials prefix
    fill_csr_kernel<<<(EE + 255) / 256, 256>>>(src, dst);

    // ---- agg(x) -> split a16 ----
    aggregate_split_kernel<<<NN, FF>>>(x);

    // ---- fused B2B: p = relu(a16 @ W1'^T + b1) @ Wf'^T ----
    b2b_kernel<<<(NN + 127) / 128, 256, 41472 * sizeof(__nv_bfloat16)>>>(
        a16, w16, wf16, b1, pbuf, NN);

    // ---- final aggregation at C=40 -> out ----
    aggregate_final_kernel<<<(NN + 7) / 8, 256>>>(out);
}